// round 12
// baseline (speedup 1.0000x reference)
#include <cuda_runtime.h>
#include <cstdint>

#define B_ 2
#define H_ 8
#define S_ 1024
#define DK_ 64
#define DV_ 64
static constexpr float INV_T = 0.125f;                   // 1/temperature
static constexpr int OUT_ATTN_OFF = B_ * H_ * S_ * DV_;  // 1048576

// ---- packed fp32 helpers (sm_103a f32x2 pipe) -------------------------------
#define FMA2(acc, a, b) asm("fma.rn.f32x2 %0, %1, %2, %0;" : "+l"(acc) : "l"(a), "l"(b))

__device__ __forceinline__ float2 unpack2(unsigned long long v) {
    float2 r;
    asm("mov.b64 {%0, %1}, %2;" : "=f"(r.x), "=f"(r.y) : "l"(v));
    return r;
}

// ---- cp.async helpers -------------------------------------------------------
__device__ __forceinline__ uint32_t s2u(const void* p) {
    return (uint32_t)__cvta_generic_to_shared(p);
}
__device__ __forceinline__ void cp8(uint32_t dst, const void* src) {
    asm volatile("cp.async.ca.shared.global [%0], [%1], 8;" :: "r"(dst), "l"(src));
}
__device__ __forceinline__ void cp16(uint32_t dst, const void* src) {
    asm volatile("cp.async.cg.shared.global [%0], [%1], 16;" :: "r"(dst), "l"(src));
}
#define CP_COMMIT() asm volatile("cp.async.commit_group;")
#define CP_WAIT0()  asm volatile("cp.async.wait_group 0;")
#define CP_WAIT1()  asm volatile("cp.async.wait_group 1;")
#define CP_WAIT2()  asm volatile("cp.async.wait_group 2;")

// ---------------------------------------------------------------------------
// K1 (measured 50us): attn1 = (q/T).k^T, d-parity packing, no transpose.
// Tile 128i x 64j, 256 threads, 8x4 micro. Split into 3 launches over bh
// slices (profiler rotation only; bh = bh0 + blockIdx.z).
// ---------------------------------------------------------------------------
static constexpr int K1_PITCH = 66;
static constexpr int K1_SMEM = (128 + 64) * K1_PITCH * 4;   // 50688 B

__global__ void __launch_bounds__(256, 2) k1_qk(const float* __restrict__ q,
                                                const float* __restrict__ k,
                                                float* __restrict__ attn,
                                                int bh0)
{
    extern __shared__ float sm1[];
    float* Qs = sm1;                    // [128][66]
    float* Ks = sm1 + 128 * K1_PITCH;   // [64][66]

    const int bh = bh0 + blockIdx.z;
    const int i0 = blockIdx.y * 128;
    const int j0 = blockIdx.x * 64;
    const float* qb = q + ((size_t)bh * S_ + i0) * DK_;
    const float* kb = k + ((size_t)bh * S_ + j0) * DK_;
    const int t = threadIdx.x;
    const uint32_t qs_u = s2u(Qs), ks_u = s2u(Ks);

    #pragma unroll
    for (int m = 0; m < 16; m++) {
        const int idx = m * 256 + t;
        const int row = idx >> 5, p = idx & 31;
        cp8(qs_u + (uint32_t)(row * K1_PITCH + 2 * p) * 4u, qb + (size_t)idx * 2);
    }
    #pragma unroll
    for (int m = 0; m < 8; m++) {
        const int idx = m * 256 + t;
        const int row = idx >> 5, p = idx & 31;
        cp8(ks_u + (uint32_t)(row * K1_PITCH + 2 * p) * 4u, kb + (size_t)idx * 2);
    }
    CP_COMMIT();
    CP_WAIT0();
    __syncthreads();

    const int tx = t & 15;
    const int ty = t >> 4;
    const float* qp = Qs + (ty * 8) * K1_PITCH;
    const float* kp = Ks + tx * K1_PITCH;

    unsigned long long acc[8][4] = {};

    #pragma unroll 8
    for (int dp = 0; dp < 32; dp++) {
        unsigned long long kv[4], qv[8];
        #pragma unroll
        for (int s = 0; s < 4; s++)
            kv[s] = *(const unsigned long long*)(kp + (16 * s) * K1_PITCH + 2 * dp);
        #pragma unroll
        for (int r = 0; r < 8; r++)
            qv[r] = *(const unsigned long long*)(qp + r * K1_PITCH + 2 * dp);
        #pragma unroll
        for (int r = 0; r < 8; r++)
            #pragma unroll
            for (int s = 0; s < 4; s++)
                FMA2(acc[r][s], qv[r], kv[s]);
    }

    #pragma unroll
    for (int r = 0; r < 8; r++) {
        float* row = attn + (((size_t)bh * S_ + i0 + ty * 8 + r) * S_) + j0;
        #pragma unroll
        for (int s = 0; s < 4; s++) {
            float2 pv = unpack2(acc[r][s]);
            row[tx + 16 * s] = (pv.x + pv.y) * INV_T;
        }
    }
}

// ---------------------------------------------------------------------------
// K2 (279-build config + 3-deep ring): per (b,i): logits = attn1 + qs.rpr;
// mask; softmax. Head-group 4 (g=t>>7), chunk 128 j, d-parity inner loop,
// 3-buffer cp16 ring (2-chunk DRAM lead), 2 CTAs/SM.
// ---------------------------------------------------------------------------
static constexpr int K2_CHUNK = 128;
static constexpr int K2_PITCH = 68;                      // 16B-aligned rows
static constexpr int K2_BUF = K2_CHUNK * K2_PITCH;       // 8704 floats
static constexpr int K2_SMEM = (576 + 3 * K2_BUF) * 4;   // 106752 B

__device__ __forceinline__ void k2_stage(uint32_t rs_u, const float* __restrict__ src,
                                         int t)
{
    #pragma unroll
    for (int m = 0; m < 8; m++) {
        const int idx = m * 256 + t;
        const int row = idx >> 4;
        const int gg  = idx & 15;
        cp16(rs_u + (uint32_t)(row * K2_PITCH + 4 * gg) * 4u, src + (size_t)idx * 4);
    }
    CP_COMMIT();
}

__global__ void __launch_bounds__(256, 2) k2_rpr_softmax(
    const float* __restrict__ q,
    const float* __restrict__ rpr,
    const int* __restrict__ mask,
    float* __restrict__ attn)
{
    extern __shared__ float sm2[];
    float* qs3   = sm2;             // [32 dp][8 h][2 e] = 512
    float* redmx = sm2 + 512;       // [8 h][4 warps]
    float* redsm = sm2 + 544;       // [8 h][4 warps]
    float* bufs  = sm2 + 576;       // 3 x [128][68]

    const int b = blockIdx.y;
    const int i = blockIdx.x;
    const int t = threadIdx.x;
    const int g = t >> 7;           // head group: heads g*4 .. g*4+3
    const int hb = g * 4;
    const int jl = t & 127;
    const int w = t >> 5, lane = t & 31;

    const float* rbase = rpr + ((size_t)b * S_ + i) * S_ * DK_;
    const int* mrow = mask + ((size_t)b * S_ + i) * S_;
    uint32_t ru[3];
    const float* rp2[3];
    #pragma unroll
    for (int n = 0; n < 3; n++) {
        rp2[n] = bufs + n * K2_BUF;
        ru[n] = s2u(rp2[n]);
    }

    // prologue: 2 chunks in flight
    k2_stage(ru[0], rbase, t);
    k2_stage(ru[1], rbase + (size_t)K2_CHUNK * DK_, t);

    // qs3[dp][h][e] = q[b,h,i,2dp+e]/T  (overlaps the staging)
    #pragma unroll
    for (int idx = t; idx < 512; idx += 256) {
        const int e = idx & 1, h = (idx >> 1) & 7, dp = idx >> 4;
        qs3[idx] = q[(((size_t)b * H_ + h) * S_ + i) * DK_ + 2 * dp + e] * INV_T;
    }

    float l[4][8];                  // [head-in-group][chunk]

    #pragma unroll
    for (int c = 0; c < 8; c++) {
        if (c) __syncthreads();     // readers of buf[(c+2)%3] (iter c-1) done

        const int j = c * K2_CHUNK + jl;
        const int mk = mrow[j];
        float a1v[4];               // attn1 prefetch (L2-hot, overlaps cp)
        #pragma unroll
        for (int hh = 0; hh < 4; hh++)
            a1v[hh] = attn[(((size_t)b * H_ + hb + hh) * S_ + i) * S_ + j];

        if (c < 6) {                // keep 2 chunks of lead in flight
            k2_stage(ru[(c + 2) % 3], rbase + (size_t)(c + 2) * K2_CHUNK * DK_, t);
            CP_WAIT2();
        } else if (c == 6) {
            CP_WAIT1();
        } else {
            CP_WAIT0();
        }
        __syncthreads();            // all threads' copies of buf[c%3] visible

        unsigned long long acc[4] = {};      // per head, packed (even-d, odd-d)
        const float* rr = rp2[c % 3] + jl * K2_PITCH;
        #pragma unroll
        for (int gg = 0; gg < 16; gg++) {
            ulonglong2 rpv = *(const ulonglong2*)(rr + 4 * gg);  // dp=2gg, 2gg+1
            const float* qb0 = qs3 + (2 * gg) * 16 + hb * 2;
            ulonglong2 qA = *(const ulonglong2*)(qb0);           // dp0: h hb,hb+1
            ulonglong2 qB = *(const ulonglong2*)(qb0 + 4);       // dp0: h hb+2,hb+3
            ulonglong2 qC = *(const ulonglong2*)(qb0 + 16);      // dp1
            ulonglong2 qD = *(const ulonglong2*)(qb0 + 20);
            FMA2(acc[0], qA.x, rpv.x);
            FMA2(acc[1], qA.y, rpv.x);
            FMA2(acc[2], qB.x, rpv.x);
            FMA2(acc[3], qB.y, rpv.x);
            FMA2(acc[0], qC.x, rpv.y);
            FMA2(acc[1], qC.y, rpv.y);
            FMA2(acc[2], qD.x, rpv.y);
            FMA2(acc[3], qD.y, rpv.y);
        }
        #pragma unroll
        for (int hh = 0; hh < 4; hh++) {
            float2 pv = unpack2(acc[hh]);
            l[hh][c] = mk ? (pv.x + pv.y + a1v[hh]) : -1e9f;
        }
    }

    // ---- block softmax: head h lives on 4 warps ----
    #pragma unroll
    for (int hh = 0; hh < 4; hh++) {
        float m = l[hh][0];
        #pragma unroll
        for (int c = 1; c < 8; c++) m = fmaxf(m, l[hh][c]);
        #pragma unroll
        for (int o = 16; o > 0; o >>= 1)
            m = fmaxf(m, __shfl_xor_sync(0xffffffffu, m, o));
        if (lane == 0) redmx[(hb + hh) * 4 + (w & 3)] = m;
    }
    __syncthreads();
    float mx[4];
    #pragma unroll
    for (int hh = 0; hh < 4; hh++) {
        const float* p = redmx + (hb + hh) * 4;
        mx[hh] = fmaxf(fmaxf(p[0], p[1]), fmaxf(p[2], p[3]));
    }
    #pragma unroll
    for (int hh = 0; hh < 4; hh++) {
        float s = 0.f;
        #pragma unroll
        for (int c = 0; c < 8; c++) {
            l[hh][c] = __expf(l[hh][c] - mx[hh]);
            s += l[hh][c];
        }
        #pragma unroll
        for (int o = 16; o > 0; o >>= 1)
            s += __shfl_xor_sync(0xffffffffu, s, o);
        if (lane == 0) redsm[(hb + hh) * 4 + (w & 3)] = s;
    }
    __syncthreads();
    #pragma unroll
    for (int hh = 0; hh < 4; hh++) {
        const float* p = redsm + (hb + hh) * 4;
        const float rinv = 1.0f / (p[0] + p[1] + p[2] + p[3]);
        float* arow = attn + (((size_t)b * H_ + hb + hh) * S_ + i) * S_;
        #pragma unroll
        for (int c = 0; c < 8; c++)
            arow[c * K2_CHUNK + jl] = l[hh][c] * rinv;
    }
}

// ---------------------------------------------------------------------------
// K3 (R9 shape @ 512 threads): output = attn @ v. j-parity packing with
// transposed V (Vt[n][j], pitch 66). Tile 128i x 64n, grid 128, 512 threads
// (16 warps/SM), 4x4 micro, j chunks of 64, double-buffered.
// ---------------------------------------------------------------------------
static constexpr int K3_PITCH = 66;
static constexpr int K3_AS = 128 * K3_PITCH;                 // 8448 floats
static constexpr int K3_VT = 64 * K3_PITCH;                  // 4224 floats
static constexpr int K3_SMEM = 2 * (K3_AS + K3_VT) * 4;      // 101376 B

__device__ __forceinline__ void k3_stage_as(uint32_t as_u, const float* __restrict__ ab,
                                            int jc, int t)
{
    // As[row][0..63] <- attn[i0+row][jc..jc+63]; 4096 cp8, 8/thread, coalesced
    #pragma unroll
    for (int m = 0; m < 8; m++) {
        const int idx = m * 512 + t;
        const int row = idx >> 5, p = idx & 31;
        cp8(as_u + (uint32_t)(row * K3_PITCH + 2 * p) * 4u,
            ab + (size_t)row * S_ + jc + 2 * p);
    }
    CP_COMMIT();
}

__global__ void __launch_bounds__(512, 1) k3_av(const float* __restrict__ attn,
                                                const float* __restrict__ v,
                                                float* __restrict__ out)
{
    extern __shared__ float sm3[];
    float* Asb[2] = { sm3,                     sm3 + (K3_AS + K3_VT) };
    float* Vtb[2] = { sm3 + K3_AS,             sm3 + (K3_AS + K3_VT) + K3_AS };

    const int bh = blockIdx.y;
    const int i0 = blockIdx.x * 128;
    const int t = threadIdx.x;
    const int tx = t & 15;       // n slots: tx + 16s
    const int ty = t >> 4;       // 0..31 -> i rows ty*4 + r
    const float* ab = attn + ((size_t)bh * S_ + i0) * S_;
    const float* vb = v + (size_t)bh * S_ * DV_;
    const uint32_t as_u[2] = { s2u(Asb[0]), s2u(Asb[1]) };

    unsigned long long acc[4][4] = {};   // [i-row r][n-slot s], packed (ej, oj)

    // prologue: prefetch v chunk 0 into regs, As chunk 0 in flight
    float4 vreg[2];
    #pragma unroll
    for (int m = 0; m < 2; m++) {
        const int idx = m * 512 + t;
        vreg[m] = *(const float4*)(vb + (size_t)(idx >> 4) * DV_ + (idx & 15) * 4);
    }
    k3_stage_as(as_u[0], ab, 0, t);

    for (int c = 0; c < 16; c++) {
        const int cur = c & 1;
        CP_WAIT0();                      // As(c) resident

        // transpose-store v chunk c: Vt[n][j]
        float* Vt = Vtb[cur];
        #pragma unroll
        for (int m = 0; m < 2; m++) {
            const int idx = m * 512 + t;
            const int vr = idx >> 4;      // j within chunk
            const int vc = idx & 15;      // n group
            Vt[(4 * vc + 0) * K3_PITCH + vr] = vreg[m].x;
            Vt[(4 * vc + 1) * K3_PITCH + vr] = vreg[m].y;
            Vt[(4 * vc + 2) * K3_PITCH + vr] = vreg[m].z;
            Vt[(4 * vc + 3) * K3_PITCH + vr] = vreg[m].w;
        }
        __syncthreads();                 // As(c) + Vt(c) visible to all

        if (c < 15) {                    // next chunk in flight during compute
            #pragma unroll
            for (int m = 0; m < 2; m++) {
                const int idx = m * 512 + t;
                vreg[m] = *(const float4*)(vb + (size_t)((c + 1) * 64 + (idx >> 4)) * DV_
                                           + (idx & 15) * 4);
            }
            k3_stage_as(as_u[cur ^ 1], ab, (c + 1) * 64, t);
        }

        const float* ap = Asb[cur] + (ty * 4) * K3_PITCH;
        const float* vp = Vt + tx * K3_PITCH;
        #pragma unroll 8
        for (int jp = 0; jp < 32; jp++) {
            unsigned long long vv[4], av[4];
            #pragma unroll
            for (int s = 0; s < 4; s++)
                vv[s] = *(const unsigned long long*)(vp + (16 * s) * K3_PITCH + 2 * jp);
            #pragma unroll
            for (int r = 0; r < 4; r++)
                av[r] = *(const unsigned long long*)(ap + r * K3_PITCH + 2 * jp);
            #pragma unroll
            for (int r = 0; r < 4; r++)
                #pragma unroll
                for (int s = 0; s < 4; s++)
                    FMA2(acc[r][s], av[r], vv[s]);
        }
        __syncthreads();                 // buf consumed before restage at c+2
    }

    #pragma unroll
    for (int r = 0; r < 4; r++) {
        float* orow = out + ((size_t)bh * S_ + i0 + ty * 4 + r) * DV_;
        #pragma unroll
        for (int s = 0; s < 4; s++) {
            float2 pv = unpack2(acc[r][s]);
            orow[tx + 16 * s] = pv.x + pv.y;
        }
    }
}

// ---------------------------------------------------------------------------
extern "C" void kernel_launch(void* const* d_in, const int* in_sizes, int n_in,
                              void* d_out, int out_size)
{
    const float* q    = (const float*)d_in[0];
    const float* k    = (const float*)d_in[1];
    const float* v    = (const float*)d_in[2];
    const int*   mask = (const int*)d_in[3];
    const float* rpr  = (const float*)d_in[4];
    float* out  = (float*)d_out;
    float* attn = out + OUT_ATTN_OFF;

    cudaFuncSetAttribute(k1_qk, cudaFuncAttributeMaxDynamicSharedMemorySize, K1_SMEM);
    cudaFuncSetAttribute(k2_rpr_softmax, cudaFuncAttributeMaxDynamicSharedMemorySize,
                         K2_SMEM);
    cudaFuncSetAttribute(k3_av, cudaFuncAttributeMaxDynamicSharedMemorySize, K3_SMEM);

    {   // K1: attn1 logits (3 launches over bh slices -> K2 is launch idx 3)
        dim3 g0(S_ / 64, S_ / 128, 6), g1(S_ / 64, S_ / 128, 5);
        k1_qk<<<g0, 256, K1_SMEM>>>(q, k, attn, 0);
        k1_qk<<<g1, 256, K1_SMEM>>>(q, k, attn, 6);
        k1_qk<<<g1, 256, K1_SMEM>>>(q, k, attn, 11);
    }
    {   // K2: + positional term, mask, softmax  (launch idx 3 -> profiled)
        dim3 grid(S_, B_);
        k2_rpr_softmax<<<grid, 256, K2_SMEM>>>(q, rpr, mask, attn);
    }
    {   // K3: output = attn @ v
        dim3 grid(S_ / 128, B_ * H_);
        k3_av<<<grid, 512, K3_SMEM>>>(attn, v, out);
    }
}

// round 13
// speedup vs baseline: 1.0411x; 1.0411x over previous
#include <cuda_runtime.h>
#include <cstdint>

#define B_ 2
#define H_ 8
#define S_ 1024
#define DK_ 64
#define DV_ 64
static constexpr float INV_T = 0.125f;                   // 1/temperature
static constexpr int OUT_ATTN_OFF = B_ * H_ * S_ * DV_;  // 1048576

// ---- packed fp32 helpers (sm_103a f32x2 pipe) -------------------------------
#define FMA2(acc, a, b) asm("fma.rn.f32x2 %0, %1, %2, %0;" : "+l"(acc) : "l"(a), "l"(b))

__device__ __forceinline__ float2 unpack2(unsigned long long v) {
    float2 r;
    asm("mov.b64 {%0, %1}, %2;" : "=f"(r.x), "=f"(r.y) : "l"(v));
    return r;
}

// ---- cp.async helpers -------------------------------------------------------
__device__ __forceinline__ uint32_t s2u(const void* p) {
    return (uint32_t)__cvta_generic_to_shared(p);
}
__device__ __forceinline__ void cp8(uint32_t dst, const void* src) {
    asm volatile("cp.async.ca.shared.global [%0], [%1], 8;" :: "r"(dst), "l"(src));
}
__device__ __forceinline__ void cp16(uint32_t dst, const void* src) {
    asm volatile("cp.async.cg.shared.global [%0], [%1], 16;" :: "r"(dst), "l"(src));
}
#define CP_COMMIT() asm volatile("cp.async.commit_group;")
#define CP_WAIT0()  asm volatile("cp.async.wait_group 0;")
#define CP_WAIT1()  asm volatile("cp.async.wait_group 1;")
#define CP_WAIT2()  asm volatile("cp.async.wait_group 2;")

// ---------------------------------------------------------------------------
// K1 (measured 50us): attn1 = (q/T).k^T, d-parity packing, no transpose.
// Tile 128i x 64j, 256 threads, 8x4 micro. Split into 3 launches over bh
// slices (profiler rotation only; bh = bh0 + blockIdx.z).
// ---------------------------------------------------------------------------
static constexpr int K1_PITCH = 66;
static constexpr int K1_SMEM = (128 + 64) * K1_PITCH * 4;   // 50688 B

__global__ void __launch_bounds__(256, 2) k1_qk(const float* __restrict__ q,
                                                const float* __restrict__ k,
                                                float* __restrict__ attn,
                                                int bh0)
{
    extern __shared__ float sm1[];
    float* Qs = sm1;                    // [128][66]
    float* Ks = sm1 + 128 * K1_PITCH;   // [64][66]

    const int bh = bh0 + blockIdx.z;
    const int i0 = blockIdx.y * 128;
    const int j0 = blockIdx.x * 64;
    const float* qb = q + ((size_t)bh * S_ + i0) * DK_;
    const float* kb = k + ((size_t)bh * S_ + j0) * DK_;
    const int t = threadIdx.x;
    const uint32_t qs_u = s2u(Qs), ks_u = s2u(Ks);

    #pragma unroll
    for (int m = 0; m < 16; m++) {
        const int idx = m * 256 + t;
        const int row = idx >> 5, p = idx & 31;
        cp8(qs_u + (uint32_t)(row * K1_PITCH + 2 * p) * 4u, qb + (size_t)idx * 2);
    }
    #pragma unroll
    for (int m = 0; m < 8; m++) {
        const int idx = m * 256 + t;
        const int row = idx >> 5, p = idx & 31;
        cp8(ks_u + (uint32_t)(row * K1_PITCH + 2 * p) * 4u, kb + (size_t)idx * 2);
    }
    CP_COMMIT();
    CP_WAIT0();
    __syncthreads();

    const int tx = t & 15;
    const int ty = t >> 4;
    const float* qp = Qs + (ty * 8) * K1_PITCH;
    const float* kp = Ks + tx * K1_PITCH;

    unsigned long long acc[8][4] = {};

    #pragma unroll 8
    for (int dp = 0; dp < 32; dp++) {
        unsigned long long kv[4], qv[8];
        #pragma unroll
        for (int s = 0; s < 4; s++)
            kv[s] = *(const unsigned long long*)(kp + (16 * s) * K1_PITCH + 2 * dp);
        #pragma unroll
        for (int r = 0; r < 8; r++)
            qv[r] = *(const unsigned long long*)(qp + r * K1_PITCH + 2 * dp);
        #pragma unroll
        for (int r = 0; r < 8; r++)
            #pragma unroll
            for (int s = 0; s < 4; s++)
                FMA2(acc[r][s], qv[r], kv[s]);
    }

    #pragma unroll
    for (int r = 0; r < 8; r++) {
        float* row = attn + (((size_t)bh * S_ + i0 + ty * 8 + r) * S_) + j0;
        #pragma unroll
        for (int s = 0; s < 4; s++) {
            float2 pv = unpack2(acc[r][s]);
            row[tx + 16 * s] = (pv.x + pv.y) * INV_T;
        }
    }
}

// ---------------------------------------------------------------------------
// K2 (279-build config + 3-deep ring): per (b,i): logits = attn1 + qs.rpr;
// mask; softmax. Head-group 4 (g=t>>7), chunk 128 j, d-parity inner loop,
// 3-buffer cp16 ring (2-chunk DRAM lead), 2 CTAs/SM.
// ---------------------------------------------------------------------------
static constexpr int K2_CHUNK = 128;
static constexpr int K2_PITCH = 68;                      // 16B-aligned rows
static constexpr int K2_BUF = K2_CHUNK * K2_PITCH;       // 8704 floats
static constexpr int K2_SMEM = (576 + 3 * K2_BUF) * 4;   // 106752 B

__device__ __forceinline__ void k2_stage(uint32_t rs_u, const float* __restrict__ src,
                                         int t)
{
    #pragma unroll
    for (int m = 0; m < 8; m++) {
        const int idx = m * 256 + t;
        const int row = idx >> 4;
        const int gg  = idx & 15;
        cp16(rs_u + (uint32_t)(row * K2_PITCH + 4 * gg) * 4u, src + (size_t)idx * 4);
    }
    CP_COMMIT();
}

__global__ void __launch_bounds__(256, 2) k2_rpr_softmax(
    const float* __restrict__ q,
    const float* __restrict__ rpr,
    const int* __restrict__ mask,
    float* __restrict__ attn)
{
    extern __shared__ float sm2[];
    float* qs3   = sm2;             // [32 dp][8 h][2 e] = 512
    float* redmx = sm2 + 512;       // [8 h][4 warps]
    float* redsm = sm2 + 544;       // [8 h][4 warps]
    float* bufs  = sm2 + 576;       // 3 x [128][68]

    const int b = blockIdx.y;
    const int i = blockIdx.x;
    const int t = threadIdx.x;
    const int g = t >> 7;           // head group: heads g*4 .. g*4+3
    const int hb = g * 4;
    const int jl = t & 127;
    const int w = t >> 5, lane = t & 31;

    const float* rbase = rpr + ((size_t)b * S_ + i) * S_ * DK_;
    const int* mrow = mask + ((size_t)b * S_ + i) * S_;
    uint32_t ru[3];
    const float* rp2[3];
    #pragma unroll
    for (int n = 0; n < 3; n++) {
        rp2[n] = bufs + n * K2_BUF;
        ru[n] = s2u(rp2[n]);
    }

    // prologue: 2 chunks in flight
    k2_stage(ru[0], rbase, t);
    k2_stage(ru[1], rbase + (size_t)K2_CHUNK * DK_, t);

    // qs3[dp][h][e] = q[b,h,i,2dp+e]/T  (overlaps the staging)
    #pragma unroll
    for (int idx = t; idx < 512; idx += 256) {
        const int e = idx & 1, h = (idx >> 1) & 7, dp = idx >> 4;
        qs3[idx] = q[(((size_t)b * H_ + h) * S_ + i) * DK_ + 2 * dp + e] * INV_T;
    }

    float l[4][8];                  // [head-in-group][chunk]

    #pragma unroll
    for (int c = 0; c < 8; c++) {
        if (c) __syncthreads();     // readers of buf[(c+2)%3] (iter c-1) done

        const int j = c * K2_CHUNK + jl;
        const int mk = mrow[j];
        float a1v[4];               // attn1 prefetch (L2-hot, overlaps cp)
        #pragma unroll
        for (int hh = 0; hh < 4; hh++)
            a1v[hh] = attn[(((size_t)b * H_ + hb + hh) * S_ + i) * S_ + j];

        if (c < 6) {                // keep 2 chunks of lead in flight
            k2_stage(ru[(c + 2) % 3], rbase + (size_t)(c + 2) * K2_CHUNK * DK_, t);
            CP_WAIT2();
        } else if (c == 6) {
            CP_WAIT1();
        } else {
            CP_WAIT0();
        }
        __syncthreads();            // all threads' copies of buf[c%3] visible

        unsigned long long acc[4] = {};      // per head, packed (even-d, odd-d)
        const float* rr = rp2[c % 3] + jl * K2_PITCH;
        #pragma unroll
        for (int gg = 0; gg < 16; gg++) {
            ulonglong2 rpv = *(const ulonglong2*)(rr + 4 * gg);  // dp=2gg, 2gg+1
            const float* qb0 = qs3 + (2 * gg) * 16 + hb * 2;
            ulonglong2 qA = *(const ulonglong2*)(qb0);           // dp0: h hb,hb+1
            ulonglong2 qB = *(const ulonglong2*)(qb0 + 4);       // dp0: h hb+2,hb+3
            ulonglong2 qC = *(const ulonglong2*)(qb0 + 16);      // dp1
            ulonglong2 qD = *(const ulonglong2*)(qb0 + 20);
            FMA2(acc[0], qA.x, rpv.x);
            FMA2(acc[1], qA.y, rpv.x);
            FMA2(acc[2], qB.x, rpv.x);
            FMA2(acc[3], qB.y, rpv.x);
            FMA2(acc[0], qC.x, rpv.y);
            FMA2(acc[1], qC.y, rpv.y);
            FMA2(acc[2], qD.x, rpv.y);
            FMA2(acc[3], qD.y, rpv.y);
        }
        #pragma unroll
        for (int hh = 0; hh < 4; hh++) {
            float2 pv = unpack2(acc[hh]);
            l[hh][c] = mk ? (pv.x + pv.y + a1v[hh]) : -1e9f;
        }
    }

    // ---- block softmax: head h lives on 4 warps ----
    #pragma unroll
    for (int hh = 0; hh < 4; hh++) {
        float m = l[hh][0];
        #pragma unroll
        for (int c = 1; c < 8; c++) m = fmaxf(m, l[hh][c]);
        #pragma unroll
        for (int o = 16; o > 0; o >>= 1)
            m = fmaxf(m, __shfl_xor_sync(0xffffffffu, m, o));
        if (lane == 0) redmx[(hb + hh) * 4 + (w & 3)] = m;
    }
    __syncthreads();
    float mx[4];
    #pragma unroll
    for (int hh = 0; hh < 4; hh++) {
        const float* p = redmx + (hb + hh) * 4;
        mx[hh] = fmaxf(fmaxf(p[0], p[1]), fmaxf(p[2], p[3]));
    }
    #pragma unroll
    for (int hh = 0; hh < 4; hh++) {
        float s = 0.f;
        #pragma unroll
        for (int c = 0; c < 8; c++) {
            l[hh][c] = __expf(l[hh][c] - mx[hh]);
            s += l[hh][c];
        }
        #pragma unroll
        for (int o = 16; o > 0; o >>= 1)
            s += __shfl_xor_sync(0xffffffffu, s, o);
        if (lane == 0) redsm[(hb + hh) * 4 + (w & 3)] = s;
    }
    __syncthreads();
    #pragma unroll
    for (int hh = 0; hh < 4; hh++) {
        const float* p = redsm + (hb + hh) * 4;
        const float rinv = 1.0f / (p[0] + p[1] + p[2] + p[3]);
        float* arow = attn + (((size_t)b * H_ + hb + hh) * S_ + i) * S_;
        #pragma unroll
        for (int c = 0; c < 8; c++)
            arow[c * K2_CHUNK + jl] = l[hh][c] * rinv;
    }
}

// ---------------------------------------------------------------------------
// K3 (R9 shape @ 512 threads): output = attn @ v. j-parity packing with
// transposed V (Vt[n][j], pitch 66). Tile 128i x 64n, grid 128, 512 threads
// (16 warps/SM), 4x4 micro, j chunks of 64, double-buffered.
// ---------------------------------------------------------------------------
static constexpr int K3_PITCH = 66;
static constexpr int K3_AS = 128 * K3_PITCH;                 // 8448 floats
static constexpr int K3_VT = 64 * K3_PITCH;                  // 4224 floats
static constexpr int K3_SMEM = 2 * (K3_AS + K3_VT) * 4;      // 101376 B

__device__ __forceinline__ void k3_stage_as(uint32_t as_u, const float* __restrict__ ab,
                                            int jc, int t)
{
    // As[row][0..63] <- attn[i0+row][jc..jc+63]; 4096 cp8, 8/thread, coalesced
    #pragma unroll
    for (int m = 0; m < 8; m++) {
        const int idx = m * 512 + t;
        const int row = idx >> 5, p = idx & 31;
        cp8(as_u + (uint32_t)(row * K3_PITCH + 2 * p) * 4u,
            ab + (size_t)row * S_ + jc + 2 * p);
    }
    CP_COMMIT();
}

__global__ void __launch_bounds__(512, 1) k3_av(const float* __restrict__ attn,
                                                const float* __restrict__ v,
                                                float* __restrict__ out)
{
    extern __shared__ float sm3[];
    float* Asb[2] = { sm3,                     sm3 + (K3_AS + K3_VT) };
    float* Vtb[2] = { sm3 + K3_AS,             sm3 + (K3_AS + K3_VT) + K3_AS };

    const int bh = blockIdx.y;
    const int i0 = blockIdx.x * 128;
    const int t = threadIdx.x;
    const int tx = t & 15;       // n slots: tx + 16s
    const int ty = t >> 4;       // 0..31 -> i rows ty*4 + r
    const float* ab = attn + ((size_t)bh * S_ + i0) * S_;
    const float* vb = v + (size_t)bh * S_ * DV_;
    const uint32_t as_u[2] = { s2u(Asb[0]), s2u(Asb[1]) };

    unsigned long long acc[4][4] = {};   // [i-row r][n-slot s], packed (ej, oj)

    // prologue: prefetch v chunk 0 into regs, As chunk 0 in flight
    float4 vreg[2];
    #pragma unroll
    for (int m = 0; m < 2; m++) {
        const int idx = m * 512 + t;
        vreg[m] = *(const float4*)(vb + (size_t)(idx >> 4) * DV_ + (idx & 15) * 4);
    }
    k3_stage_as(as_u[0], ab, 0, t);

    for (int c = 0; c < 16; c++) {
        const int cur = c & 1;
        CP_WAIT0();                      // As(c) resident

        // transpose-store v chunk c: Vt[n][j]
        float* Vt = Vtb[cur];
        #pragma unroll
        for (int m = 0; m < 2; m++) {
            const int idx = m * 512 + t;
            const int vr = idx >> 4;      // j within chunk
            const int vc = idx & 15;      // n group
            Vt[(4 * vc + 0) * K3_PITCH + vr] = vreg[m].x;
            Vt[(4 * vc + 1) * K3_PITCH + vr] = vreg[m].y;
            Vt[(4 * vc + 2) * K3_PITCH + vr] = vreg[m].z;
            Vt[(4 * vc + 3) * K3_PITCH + vr] = vreg[m].w;
        }
        __syncthreads();                 // As(c) + Vt(c) visible to all

        if (c < 15) {                    // next chunk in flight during compute
            #pragma unroll
            for (int m = 0; m < 2; m++) {
                const int idx = m * 512 + t;
                vreg[m] = *(const float4*)(vb + (size_t)((c + 1) * 64 + (idx >> 4)) * DV_
                                           + (idx & 15) * 4);
            }
            k3_stage_as(as_u[cur ^ 1], ab, (c + 1) * 64, t);
        }

        const float* ap = Asb[cur] + (ty * 4) * K3_PITCH;
        const float* vp = Vt + tx * K3_PITCH;
        #pragma unroll 8
        for (int jp = 0; jp < 32; jp++) {
            unsigned long long vv[4], av[4];
            #pragma unroll
            for (int s = 0; s < 4; s++)
                vv[s] = *(const unsigned long long*)(vp + (16 * s) * K3_PITCH + 2 * jp);
            #pragma unroll
            for (int r = 0; r < 4; r++)
                av[r] = *(const unsigned long long*)(ap + r * K3_PITCH + 2 * jp);
            #pragma unroll
            for (int r = 0; r < 4; r++)
                #pragma unroll
                for (int s = 0; s < 4; s++)
                    FMA2(acc[r][s], av[r], vv[s]);
        }
        __syncthreads();                 // buf consumed before restage at c+2
    }

    #pragma unroll
    for (int r = 0; r < 4; r++) {
        float* orow = out + ((size_t)bh * S_ + i0 + ty * 4 + r) * DV_;
        #pragma unroll
        for (int s = 0; s < 4; s++) {
            float2 pv = unpack2(acc[r][s]);
            orow[tx + 16 * s] = pv.x + pv.y;
        }
    }
}

// ---------------------------------------------------------------------------
extern "C" void kernel_launch(void* const* d_in, const int* in_sizes, int n_in,
                              void* d_out, int out_size)
{
    const float* q    = (const float*)d_in[0];
    const float* k    = (const float*)d_in[1];
    const float* v    = (const float*)d_in[2];
    const int*   mask = (const int*)d_in[3];
    const float* rpr  = (const float*)d_in[4];
    float* out  = (float*)d_out;
    float* attn = out + OUT_ATTN_OFF;

    cudaFuncSetAttribute(k1_qk, cudaFuncAttributeMaxDynamicSharedMemorySize, K1_SMEM);
    cudaFuncSetAttribute(k2_rpr_softmax, cudaFuncAttributeMaxDynamicSharedMemorySize,
                         K2_SMEM);
    cudaFuncSetAttribute(k3_av, cudaFuncAttributeMaxDynamicSharedMemorySize, K3_SMEM);

    {   // K1: attn1 logits (3 launches over bh slices -> K2 is launch idx 3)
        dim3 g0(S_ / 64, S_ / 128, 6), g1(S_ / 64, S_ / 128, 5);
        k1_qk<<<g0, 256, K1_SMEM>>>(q, k, attn, 0);
        k1_qk<<<g1, 256, K1_SMEM>>>(q, k, attn, 6);
        k1_qk<<<g1, 256, K1_SMEM>>>(q, k, attn, 11);
    }
    {   // K2: + positional term, mask, softmax  (launch idx 3 -> profiled)
        dim3 grid(S_, B_);
        k2_rpr_softmax<<<grid, 256, K2_SMEM>>>(q, rpr, mask, attn);
    }
    {   // K3: output = attn @ v
        dim3 grid(S_ / 128, B_ * H_);
        k3_av<<<grid, 512, K3_SMEM>>>(attn, v, out);
    }
}

// round 14
// speedup vs baseline: 1.0524x; 1.0109x over previous
#include <cuda_runtime.h>
#include <cstdint>

#define B_ 2
#define H_ 8
#define S_ 1024
#define DK_ 64
#define DV_ 64
static constexpr float INV_T = 0.125f;                   // 1/temperature
static constexpr int OUT_ATTN_OFF = B_ * H_ * S_ * DV_;  // 1048576

// 4 MB transposed-V scratch: g_vt[bh][n][j] = v[bh][j][n]
__device__ float g_vt[B_ * H_ * DV_ * S_];

// ---- packed fp32 helpers (sm_103a f32x2 pipe) -------------------------------
#define FMA2(acc, a, b) asm("fma.rn.f32x2 %0, %1, %2, %0;" : "+l"(acc) : "l"(a), "l"(b))

__device__ __forceinline__ float2 unpack2(unsigned long long v) {
    float2 r;
    asm("mov.b64 {%0, %1}, %2;" : "=f"(r.x), "=f"(r.y) : "l"(v));
    return r;
}

// ---- cp.async helpers -------------------------------------------------------
__device__ __forceinline__ uint32_t s2u(const void* p) {
    return (uint32_t)__cvta_generic_to_shared(p);
}
__device__ __forceinline__ void cp8(uint32_t dst, const void* src) {
    asm volatile("cp.async.ca.shared.global [%0], [%1], 8;" :: "r"(dst), "l"(src));
}
__device__ __forceinline__ void cp16(uint32_t dst, const void* src) {
    asm volatile("cp.async.cg.shared.global [%0], [%1], 16;" :: "r"(dst), "l"(src));
}
#define CP_COMMIT() asm volatile("cp.async.commit_group;")
#define CP_WAIT0()  asm volatile("cp.async.wait_group 0;")
#define CP_WAIT1()  asm volatile("cp.async.wait_group 1;")
#define CP_WAIT2()  asm volatile("cp.async.wait_group 2;")

// ---------------------------------------------------------------------------
// K1 (measured 50us, UNCHANGED): attn1 = (q/T).k^T, d-parity packing.
// Tile 128i x 64j, 256 threads, 8x4 micro (j strided by 16), pitch 66.
// ---------------------------------------------------------------------------
static constexpr int K1_PITCH = 66;
static constexpr int K1_SMEM = (128 + 64) * K1_PITCH * 4;   // 50688 B

__global__ void __launch_bounds__(256, 2) k1_qk(const float* __restrict__ q,
                                                const float* __restrict__ k,
                                                float* __restrict__ attn)
{
    extern __shared__ float sm1[];
    float* Qs = sm1;                    // [128][66]
    float* Ks = sm1 + 128 * K1_PITCH;   // [64][66]

    const int bh = blockIdx.z;
    const int i0 = blockIdx.y * 128;
    const int j0 = blockIdx.x * 64;
    const float* qb = q + ((size_t)bh * S_ + i0) * DK_;
    const float* kb = k + ((size_t)bh * S_ + j0) * DK_;
    const int t = threadIdx.x;
    const uint32_t qs_u = s2u(Qs), ks_u = s2u(Ks);

    #pragma unroll
    for (int m = 0; m < 16; m++) {
        const int idx = m * 256 + t;
        const int row = idx >> 5, p = idx & 31;
        cp8(qs_u + (uint32_t)(row * K1_PITCH + 2 * p) * 4u, qb + (size_t)idx * 2);
    }
    #pragma unroll
    for (int m = 0; m < 8; m++) {
        const int idx = m * 256 + t;
        const int row = idx >> 5, p = idx & 31;
        cp8(ks_u + (uint32_t)(row * K1_PITCH + 2 * p) * 4u, kb + (size_t)idx * 2);
    }
    CP_COMMIT();
    CP_WAIT0();
    __syncthreads();

    const int tx = t & 15;
    const int ty = t >> 4;
    const float* qp = Qs + (ty * 8) * K1_PITCH;
    const float* kp = Ks + tx * K1_PITCH;

    unsigned long long acc[8][4] = {};

    #pragma unroll 8
    for (int dp = 0; dp < 32; dp++) {
        unsigned long long kv[4], qv[8];
        #pragma unroll
        for (int s = 0; s < 4; s++)
            kv[s] = *(const unsigned long long*)(kp + (16 * s) * K1_PITCH + 2 * dp);
        #pragma unroll
        for (int r = 0; r < 8; r++)
            qv[r] = *(const unsigned long long*)(qp + r * K1_PITCH + 2 * dp);
        #pragma unroll
        for (int r = 0; r < 8; r++)
            #pragma unroll
            for (int s = 0; s < 4; s++)
                FMA2(acc[r][s], qv[r], kv[s]);
    }

    #pragma unroll
    for (int r = 0; r < 8; r++) {
        float* row = attn + (((size_t)bh * S_ + i0 + ty * 8 + r) * S_) + j0;
        #pragma unroll
        for (int s = 0; s < 4; s++) {
            float2 pv = unpack2(acc[r][s]);
            row[tx + 16 * s] = (pv.x + pv.y) * INV_T;
        }
    }
}

// ---------------------------------------------------------------------------
// K0t: one-time transpose v -> g_vt[bh][n][j]. 64j x 64n tiles, grid (16,16).
// ---------------------------------------------------------------------------
__global__ void __launch_bounds__(256) k0_vt(const float* __restrict__ v)
{
    __shared__ float ts[64][65];
    const int j0 = blockIdx.x * 64;
    const int bh = blockIdx.y;
    const int t = threadIdx.x;
    const float* vb = v + (size_t)bh * S_ * DV_;

    #pragma unroll
    for (int m = 0; m < 4; m++) {
        const int idx = m * 256 + t;
        const int row = idx >> 4, g = idx & 15;
        float4 a = *(const float4*)(vb + (size_t)(j0 + row) * DV_ + 4 * g);
        ts[row][4 * g + 0] = a.x;
        ts[row][4 * g + 1] = a.y;
        ts[row][4 * g + 2] = a.z;
        ts[row][4 * g + 3] = a.w;
    }
    __syncthreads();

    float* dst = g_vt + (size_t)bh * DV_ * S_;
    #pragma unroll
    for (int m = 0; m < 4; m++) {
        const int idx = m * 256 + t;
        const int n = idx >> 4, jq = idx & 15;
        float4 w = make_float4(ts[4 * jq + 0][n], ts[4 * jq + 1][n],
                               ts[4 * jq + 2][n], ts[4 * jq + 3][n]);
        *(float4*)(dst + (size_t)n * S_ + j0 + 4 * jq) = w;
    }
}

// ---------------------------------------------------------------------------
// K2 (measured 137us, UNCHANGED): logits = attn1 + qs.rpr; mask; softmax.
// Head-group 4, chunk 128 j, d-parity, 3-buffer cp16 ring, 2 CTAs/SM.
// ---------------------------------------------------------------------------
static constexpr int K2_CHUNK = 128;
static constexpr int K2_PITCH = 68;                      // 16B-aligned rows
static constexpr int K2_BUF = K2_CHUNK * K2_PITCH;       // 8704 floats
static constexpr int K2_SMEM = (576 + 3 * K2_BUF) * 4;   // 106752 B

__device__ __forceinline__ void k2_stage(uint32_t rs_u, const float* __restrict__ src,
                                         int t)
{
    #pragma unroll
    for (int m = 0; m < 8; m++) {
        const int idx = m * 256 + t;
        const int row = idx >> 4;
        const int gg  = idx & 15;
        cp16(rs_u + (uint32_t)(row * K2_PITCH + 4 * gg) * 4u, src + (size_t)idx * 4);
    }
    CP_COMMIT();
}

__global__ void __launch_bounds__(256, 2) k2_rpr_softmax(
    const float* __restrict__ q,
    const float* __restrict__ rpr,
    const int* __restrict__ mask,
    float* __restrict__ attn)
{
    extern __shared__ float sm2[];
    float* qs3   = sm2;             // [32 dp][8 h][2 e] = 512
    float* redmx = sm2 + 512;       // [8 h][4 warps]
    float* redsm = sm2 + 544;       // [8 h][4 warps]
    float* bufs  = sm2 + 576;       // 3 x [128][68]

    const int b = blockIdx.y;
    const int i = blockIdx.x;
    const int t = threadIdx.x;
    const int g = t >> 7;           // head group: heads g*4 .. g*4+3
    const int hb = g * 4;
    const int jl = t & 127;
    const int w = t >> 5, lane = t & 31;

    const float* rbase = rpr + ((size_t)b * S_ + i) * S_ * DK_;
    const int* mrow = mask + ((size_t)b * S_ + i) * S_;
    uint32_t ru[3];
    const float* rp2[3];
    #pragma unroll
    for (int n = 0; n < 3; n++) {
        rp2[n] = bufs + n * K2_BUF;
        ru[n] = s2u(rp2[n]);
    }

    k2_stage(ru[0], rbase, t);
    k2_stage(ru[1], rbase + (size_t)K2_CHUNK * DK_, t);

    #pragma unroll
    for (int idx = t; idx < 512; idx += 256) {
        const int e = idx & 1, h = (idx >> 1) & 7, dp = idx >> 4;
        qs3[idx] = q[(((size_t)b * H_ + h) * S_ + i) * DK_ + 2 * dp + e] * INV_T;
    }

    float l[4][8];                  // [head-in-group][chunk]

    #pragma unroll
    for (int c = 0; c < 8; c++) {
        if (c) __syncthreads();

        const int j = c * K2_CHUNK + jl;
        const int mk = mrow[j];
        float a1v[4];
        #pragma unroll
        for (int hh = 0; hh < 4; hh++)
            a1v[hh] = attn[(((size_t)b * H_ + hb + hh) * S_ + i) * S_ + j];

        if (c < 6) {
            k2_stage(ru[(c + 2) % 3], rbase + (size_t)(c + 2) * K2_CHUNK * DK_, t);
            CP_WAIT2();
        } else if (c == 6) {
            CP_WAIT1();
        } else {
            CP_WAIT0();
        }
        __syncthreads();

        unsigned long long acc[4] = {};
        const float* rr = rp2[c % 3] + jl * K2_PITCH;
        #pragma unroll
        for (int gg = 0; gg < 16; gg++) {
            ulonglong2 rpv = *(const ulonglong2*)(rr + 4 * gg);
            const float* qb0 = qs3 + (2 * gg) * 16 + hb * 2;
            ulonglong2 qA = *(const ulonglong2*)(qb0);
            ulonglong2 qB = *(const ulonglong2*)(qb0 + 4);
            ulonglong2 qC = *(const ulonglong2*)(qb0 + 16);
            ulonglong2 qD = *(const ulonglong2*)(qb0 + 20);
            FMA2(acc[0], qA.x, rpv.x);
            FMA2(acc[1], qA.y, rpv.x);
            FMA2(acc[2], qB.x, rpv.x);
            FMA2(acc[3], qB.y, rpv.x);
            FMA2(acc[0], qC.x, rpv.y);
            FMA2(acc[1], qC.y, rpv.y);
            FMA2(acc[2], qD.x, rpv.y);
            FMA2(acc[3], qD.y, rpv.y);
        }
        #pragma unroll
        for (int hh = 0; hh < 4; hh++) {
            float2 pv = unpack2(acc[hh]);
            l[hh][c] = mk ? (pv.x + pv.y + a1v[hh]) : -1e9f;
        }
    }

    // ---- block softmax ----
    #pragma unroll
    for (int hh = 0; hh < 4; hh++) {
        float m = l[hh][0];
        #pragma unroll
        for (int c = 1; c < 8; c++) m = fmaxf(m, l[hh][c]);
        #pragma unroll
        for (int o = 16; o > 0; o >>= 1)
            m = fmaxf(m, __shfl_xor_sync(0xffffffffu, m, o));
        if (lane == 0) redmx[(hb + hh) * 4 + (w & 3)] = m;
    }
    __syncthreads();
    float mx[4];
    #pragma unroll
    for (int hh = 0; hh < 4; hh++) {
        const float* p = redmx + (hb + hh) * 4;
        mx[hh] = fmaxf(fmaxf(p[0], p[1]), fmaxf(p[2], p[3]));
    }
    #pragma unroll
    for (int hh = 0; hh < 4; hh++) {
        float s = 0.f;
        #pragma unroll
        for (int c = 0; c < 8; c++) {
            l[hh][c] = __expf(l[hh][c] - mx[hh]);
            s += l[hh][c];
        }
        #pragma unroll
        for (int o = 16; o > 0; o >>= 1)
            s += __shfl_xor_sync(0xffffffffu, s, o);
        if (lane == 0) redsm[(hb + hh) * 4 + (w & 3)] = s;
    }
    __syncthreads();
    #pragma unroll
    for (int hh = 0; hh < 4; hh++) {
        const float* p = redsm + (hb + hh) * 4;
        const float rinv = 1.0f / (p[0] + p[1] + p[2] + p[3]);
        float* arow = attn + (((size_t)b * H_ + hb + hh) * S_ + i) * S_;
        #pragma unroll
        for (int c = 0; c < 8; c++)
            arow[c * K2_CHUNK + jl] = l[hh][c] * rinv;
    }
}

// ---------------------------------------------------------------------------
// K3 (REBUILT as exact K1 clone): output = attn @ v via pre-transposed g_vt.
// Tile 64i x 64n, 256 threads, 4x4 micro (n strided by 16), pitch 66,
// j chunks of 64, 2-deep cp8 ring, 2 CTAs/SM. No in-loop transpose.
// ---------------------------------------------------------------------------
static constexpr int K3_PITCH = 66;
static constexpr int K3_BUF = 64 * K3_PITCH;                  // 4224 floats
static constexpr int K3_SMEM = 4 * K3_BUF * 4;                // 67584 B

__device__ __forceinline__ void k3_stage(uint32_t as_u, uint32_t vs_u,
                                         const float* __restrict__ ab,
                                         const float* __restrict__ vtb,
                                         int jc, int t)
{
    #pragma unroll
    for (int m = 0; m < 8; m++) {
        const int idx = m * 256 + t;
        const int row = idx >> 5, p = idx & 31;
        cp8(as_u + (uint32_t)(row * K3_PITCH + 2 * p) * 4u,
            ab + (size_t)row * S_ + jc + 2 * p);
    }
    #pragma unroll
    for (int m = 0; m < 8; m++) {
        const int idx = m * 256 + t;
        const int row = idx >> 5, p = idx & 31;
        cp8(vs_u + (uint32_t)(row * K3_PITCH + 2 * p) * 4u,
            vtb + (size_t)row * S_ + jc + 2 * p);
    }
    CP_COMMIT();
}

__global__ void __launch_bounds__(256, 2) k3_av(const float* __restrict__ attn,
                                                float* __restrict__ out)
{
    extern __shared__ float sm3[];
    // ring layout: [As0][Vs0][As1][Vs1]
    float* Asb[2] = { sm3,              sm3 + 2 * K3_BUF };
    float* Vsb[2] = { sm3 + K3_BUF,     sm3 + 3 * K3_BUF };

    const int bh = blockIdx.y;
    const int i0 = blockIdx.x * 64;
    const int t = threadIdx.x;
    const int tx = t & 15;       // n slots: tx + 16s
    const int ty = t >> 4;       // i rows: ty*4 + r
    const float* ab = attn + ((size_t)bh * S_ + i0) * S_;
    const float* vtb = g_vt + (size_t)bh * DV_ * S_;
    const uint32_t as_u[2] = { s2u(Asb[0]), s2u(Asb[1]) };
    const uint32_t vs_u[2] = { s2u(Vsb[0]), s2u(Vsb[1]) };

    unsigned long long acc[4][4] = {};   // [i-row r][n-slot s], packed (ej, oj)

    k3_stage(as_u[0], vs_u[0], ab, vtb, 0, t);

    for (int c = 0; c < 16; c++) {
        if (c) __syncthreads();          // readers of buf (c+1)&1 (iter c-1) done
        if (c < 15) {
            k3_stage(as_u[(c + 1) & 1], vs_u[(c + 1) & 1], ab, vtb, (c + 1) * 64, t);
            CP_WAIT1();
        } else {
            CP_WAIT0();
        }
        __syncthreads();                 // buf c&1 visible to all

        const float* ap = Asb[c & 1] + (ty * 4) * K3_PITCH;
        const float* vp = Vsb[c & 1] + tx * K3_PITCH;
        #pragma unroll 8
        for (int jp = 0; jp < 32; jp++) {
            unsigned long long vv[4], av[4];
            #pragma unroll
            for (int s = 0; s < 4; s++)
                vv[s] = *(const unsigned long long*)(vp + (16 * s) * K3_PITCH + 2 * jp);
            #pragma unroll
            for (int r = 0; r < 4; r++)
                av[r] = *(const unsigned long long*)(ap + r * K3_PITCH + 2 * jp);
            #pragma unroll
            for (int r = 0; r < 4; r++)
                #pragma unroll
                for (int s = 0; s < 4; s++)
                    FMA2(acc[r][s], av[r], vv[s]);
        }
    }

    #pragma unroll
    for (int r = 0; r < 4; r++) {
        float* orow = out + ((size_t)bh * S_ + i0 + ty * 4 + r) * DV_;
        #pragma unroll
        for (int s = 0; s < 4; s++) {
            float2 pv = unpack2(acc[r][s]);
            orow[tx + 16 * s] = pv.x + pv.y;
        }
    }
}

// ---------------------------------------------------------------------------
extern "C" void kernel_launch(void* const* d_in, const int* in_sizes, int n_in,
                              void* d_out, int out_size)
{
    const float* q    = (const float*)d_in[0];
    const float* k    = (const float*)d_in[1];
    const float* v    = (const float*)d_in[2];
    const int*   mask = (const int*)d_in[3];
    const float* rpr  = (const float*)d_in[4];
    float* out  = (float*)d_out;
    float* attn = out + OUT_ATTN_OFF;

    cudaFuncSetAttribute(k1_qk, cudaFuncAttributeMaxDynamicSharedMemorySize, K1_SMEM);
    cudaFuncSetAttribute(k2_rpr_softmax, cudaFuncAttributeMaxDynamicSharedMemorySize,
                         K2_SMEM);
    cudaFuncSetAttribute(k3_av, cudaFuncAttributeMaxDynamicSharedMemorySize, K3_SMEM);

    {   // launch 0 — K1: attn1 logits into attn region
        dim3 grid(S_ / 64, S_ / 128, B_ * H_);
        k1_qk<<<grid, 256, K1_SMEM>>>(q, k, attn);
    }
    {   // launch 1 — K0t: transpose v into g_vt (independent of K1)
        dim3 grid(S_ / 64, B_ * H_);
        k0_vt<<<grid, 256>>>(v);
    }
    {   // launch 2 — K2: + positional term, mask, softmax
        dim3 grid(S_, B_);
        k2_rpr_softmax<<<grid, 256, K2_SMEM>>>(q, rpr, mask, attn);
    }
    {   // launch 3 (profiled) — K3: output = attn @ v
        dim3 grid(S_ / 64, B_ * H_);
        k3_av<<<grid, 256, K3_SMEM>>>(attn, out);
    }
}

// round 15
// speedup vs baseline: 1.0679x; 1.0147x over previous
#include <cuda_runtime.h>
#include <cstdint>

#define B_ 2
#define H_ 8
#define S_ 1024
#define DK_ 64
#define DV_ 64
static constexpr float INV_T = 0.125f;                   // 1/temperature
static constexpr int OUT_ATTN_OFF = B_ * H_ * S_ * DV_;  // 1048576

// 4 MB transposed-V scratch: g_vt[bh][n][j] = v[bh][j][n]
__device__ float g_vt[B_ * H_ * DV_ * S_];

// ---- packed fp32 helpers (sm_103a f32x2 pipe) -------------------------------
#define FMA2(acc, a, b) asm("fma.rn.f32x2 %0, %1, %2, %0;" : "+l"(acc) : "l"(a), "l"(b))

__device__ __forceinline__ float2 unpack2(unsigned long long v) {
    float2 r;
    asm("mov.b64 {%0, %1}, %2;" : "=f"(r.x), "=f"(r.y) : "l"(v));
    return r;
}

// ---- cp.async helpers -------------------------------------------------------
__device__ __forceinline__ uint32_t s2u(const void* p) {
    return (uint32_t)__cvta_generic_to_shared(p);
}
__device__ __forceinline__ void cp8(uint32_t dst, const void* src) {
    asm volatile("cp.async.ca.shared.global [%0], [%1], 8;" :: "r"(dst), "l"(src));
}
__device__ __forceinline__ void cp16(uint32_t dst, const void* src) {
    asm volatile("cp.async.cg.shared.global [%0], [%1], 16;" :: "r"(dst), "l"(src));
}
#define CP_COMMIT() asm volatile("cp.async.commit_group;")
#define CP_WAIT0()  asm volatile("cp.async.wait_group 0;")
#define CP_WAIT1()  asm volatile("cp.async.wait_group 1;")
#define CP_WAIT2()  asm volatile("cp.async.wait_group 2;")

// ---------------------------------------------------------------------------
// K1 (measured 50us, UNCHANGED): attn1 = (q/T).k^T, d-parity packing.
// Tile 128i x 64j, 256 threads, 8x4 micro (j strided by 16), pitch 66.
// ---------------------------------------------------------------------------
static constexpr int K1_PITCH = 66;
static constexpr int K1_SMEM = (128 + 64) * K1_PITCH * 4;   // 50688 B

__global__ void __launch_bounds__(256, 2) k1_qk(const float* __restrict__ q,
                                                const float* __restrict__ k,
                                                float* __restrict__ attn)
{
    extern __shared__ float sm1[];
    float* Qs = sm1;                    // [128][66]
    float* Ks = sm1 + 128 * K1_PITCH;   // [64][66]

    const int bh = blockIdx.z;
    const int i0 = blockIdx.y * 128;
    const int j0 = blockIdx.x * 64;
    const float* qb = q + ((size_t)bh * S_ + i0) * DK_;
    const float* kb = k + ((size_t)bh * S_ + j0) * DK_;
    const int t = threadIdx.x;
    const uint32_t qs_u = s2u(Qs), ks_u = s2u(Ks);

    #pragma unroll
    for (int m = 0; m < 16; m++) {
        const int idx = m * 256 + t;
        const int row = idx >> 5, p = idx & 31;
        cp8(qs_u + (uint32_t)(row * K1_PITCH + 2 * p) * 4u, qb + (size_t)idx * 2);
    }
    #pragma unroll
    for (int m = 0; m < 8; m++) {
        const int idx = m * 256 + t;
        const int row = idx >> 5, p = idx & 31;
        cp8(ks_u + (uint32_t)(row * K1_PITCH + 2 * p) * 4u, kb + (size_t)idx * 2);
    }
    CP_COMMIT();
    CP_WAIT0();
    __syncthreads();

    const int tx = t & 15;
    const int ty = t >> 4;
    const float* qp = Qs + (ty * 8) * K1_PITCH;
    const float* kp = Ks + tx * K1_PITCH;

    unsigned long long acc[8][4] = {};

    #pragma unroll 8
    for (int dp = 0; dp < 32; dp++) {
        unsigned long long kv[4], qv[8];
        #pragma unroll
        for (int s = 0; s < 4; s++)
            kv[s] = *(const unsigned long long*)(kp + (16 * s) * K1_PITCH + 2 * dp);
        #pragma unroll
        for (int r = 0; r < 8; r++)
            qv[r] = *(const unsigned long long*)(qp + r * K1_PITCH + 2 * dp);
        #pragma unroll
        for (int r = 0; r < 8; r++)
            #pragma unroll
            for (int s = 0; s < 4; s++)
                FMA2(acc[r][s], qv[r], kv[s]);
    }

    #pragma unroll
    for (int r = 0; r < 8; r++) {
        float* row = attn + (((size_t)bh * S_ + i0 + ty * 8 + r) * S_) + j0;
        #pragma unroll
        for (int s = 0; s < 4; s++) {
            float2 pv = unpack2(acc[r][s]);
            row[tx + 16 * s] = (pv.x + pv.y) * INV_T;
        }
    }
}

// ---------------------------------------------------------------------------
// K0t: one-time transpose v -> g_vt[bh][n][j]. 64j x 64n tiles.
// ---------------------------------------------------------------------------
__global__ void __launch_bounds__(256) k0_vt(const float* __restrict__ v)
{
    __shared__ float ts[64][65];
    const int j0 = blockIdx.x * 64;
    const int bh = blockIdx.y;
    const int t = threadIdx.x;
    const float* vb = v + (size_t)bh * S_ * DV_;

    #pragma unroll
    for (int m = 0; m < 4; m++) {
        const int idx = m * 256 + t;
        const int row = idx >> 4, g = idx & 15;
        float4 a = *(const float4*)(vb + (size_t)(j0 + row) * DV_ + 4 * g);
        ts[row][4 * g + 0] = a.x;
        ts[row][4 * g + 1] = a.y;
        ts[row][4 * g + 2] = a.z;
        ts[row][4 * g + 3] = a.w;
    }
    __syncthreads();

    float* dst = g_vt + (size_t)bh * DV_ * S_;
    #pragma unroll
    for (int m = 0; m < 4; m++) {
        const int idx = m * 256 + t;
        const int n = idx >> 4, jq = idx & 15;
        float4 w = make_float4(ts[4 * jq + 0][n], ts[4 * jq + 1][n],
                               ts[4 * jq + 2][n], ts[4 * jq + 3][n]);
        *(float4*)(dst + (size_t)n * S_ + j0 + 4 * jq) = w;
    }
}

// ---------------------------------------------------------------------------
// K2 (measured 137us, UNCHANGED): logits = attn1 + qs.rpr; mask; softmax.
// Head-group 4, chunk 128 j, d-parity, 3-buffer cp16 ring, 2 CTAs/SM.
// ---------------------------------------------------------------------------
static constexpr int K2_CHUNK = 128;
static constexpr int K2_PITCH = 68;                      // 16B-aligned rows
static constexpr int K2_BUF = K2_CHUNK * K2_PITCH;       // 8704 floats
static constexpr int K2_SMEM = (576 + 3 * K2_BUF) * 4;   // 106752 B

__device__ __forceinline__ void k2_stage(uint32_t rs_u, const float* __restrict__ src,
                                         int t)
{
    #pragma unroll
    for (int m = 0; m < 8; m++) {
        const int idx = m * 256 + t;
        const int row = idx >> 4;
        const int gg  = idx & 15;
        cp16(rs_u + (uint32_t)(row * K2_PITCH + 4 * gg) * 4u, src + (size_t)idx * 4);
    }
    CP_COMMIT();
}

__global__ void __launch_bounds__(256, 2) k2_rpr_softmax(
    const float* __restrict__ q,
    const float* __restrict__ rpr,
    const int* __restrict__ mask,
    float* __restrict__ attn)
{
    extern __shared__ float sm2[];
    float* qs3   = sm2;             // [32 dp][8 h][2 e] = 512
    float* redmx = sm2 + 512;       // [8 h][4 warps]
    float* redsm = sm2 + 544;       // [8 h][4 warps]
    float* bufs  = sm2 + 576;       // 3 x [128][68]

    const int b = blockIdx.y;
    const int i = blockIdx.x;
    const int t = threadIdx.x;
    const int g = t >> 7;           // head group: heads g*4 .. g*4+3
    const int hb = g * 4;
    const int jl = t & 127;
    const int w = t >> 5, lane = t & 31;

    const float* rbase = rpr + ((size_t)b * S_ + i) * S_ * DK_;
    const int* mrow = mask + ((size_t)b * S_ + i) * S_;
    uint32_t ru[3];
    const float* rp2[3];
    #pragma unroll
    for (int n = 0; n < 3; n++) {
        rp2[n] = bufs + n * K2_BUF;
        ru[n] = s2u(rp2[n]);
    }

    k2_stage(ru[0], rbase, t);
    k2_stage(ru[1], rbase + (size_t)K2_CHUNK * DK_, t);

    #pragma unroll
    for (int idx = t; idx < 512; idx += 256) {
        const int e = idx & 1, h = (idx >> 1) & 7, dp = idx >> 4;
        qs3[idx] = q[(((size_t)b * H_ + h) * S_ + i) * DK_ + 2 * dp + e] * INV_T;
    }

    float l[4][8];                  // [head-in-group][chunk]

    #pragma unroll
    for (int c = 0; c < 8; c++) {
        if (c) __syncthreads();

        const int j = c * K2_CHUNK + jl;
        const int mk = mrow[j];
        float a1v[4];
        #pragma unroll
        for (int hh = 0; hh < 4; hh++)
            a1v[hh] = attn[(((size_t)b * H_ + hb + hh) * S_ + i) * S_ + j];

        if (c < 6) {
            k2_stage(ru[(c + 2) % 3], rbase + (size_t)(c + 2) * K2_CHUNK * DK_, t);
            CP_WAIT2();
        } else if (c == 6) {
            CP_WAIT1();
        } else {
            CP_WAIT0();
        }
        __syncthreads();

        unsigned long long acc[4] = {};
        const float* rr = rp2[c % 3] + jl * K2_PITCH;
        #pragma unroll
        for (int gg = 0; gg < 16; gg++) {
            ulonglong2 rpv = *(const ulonglong2*)(rr + 4 * gg);
            const float* qb0 = qs3 + (2 * gg) * 16 + hb * 2;
            ulonglong2 qA = *(const ulonglong2*)(qb0);
            ulonglong2 qB = *(const ulonglong2*)(qb0 + 4);
            ulonglong2 qC = *(const ulonglong2*)(qb0 + 16);
            ulonglong2 qD = *(const ulonglong2*)(qb0 + 20);
            FMA2(acc[0], qA.x, rpv.x);
            FMA2(acc[1], qA.y, rpv.x);
            FMA2(acc[2], qB.x, rpv.x);
            FMA2(acc[3], qB.y, rpv.x);
            FMA2(acc[0], qC.x, rpv.y);
            FMA2(acc[1], qC.y, rpv.y);
            FMA2(acc[2], qD.x, rpv.y);
            FMA2(acc[3], qD.y, rpv.y);
        }
        #pragma unroll
        for (int hh = 0; hh < 4; hh++) {
            float2 pv = unpack2(acc[hh]);
            l[hh][c] = mk ? (pv.x + pv.y + a1v[hh]) : -1e9f;
        }
    }

    // ---- block softmax ----
    #pragma unroll
    for (int hh = 0; hh < 4; hh++) {
        float m = l[hh][0];
        #pragma unroll
        for (int c = 1; c < 8; c++) m = fmaxf(m, l[hh][c]);
        #pragma unroll
        for (int o = 16; o > 0; o >>= 1)
            m = fmaxf(m, __shfl_xor_sync(0xffffffffu, m, o));
        if (lane == 0) redmx[(hb + hh) * 4 + (w & 3)] = m;
    }
    __syncthreads();
    float mx[4];
    #pragma unroll
    for (int hh = 0; hh < 4; hh++) {
        const float* p = redmx + (hb + hh) * 4;
        mx[hh] = fmaxf(fmaxf(p[0], p[1]), fmaxf(p[2], p[3]));
    }
    #pragma unroll
    for (int hh = 0; hh < 4; hh++) {
        float s = 0.f;
        #pragma unroll
        for (int c = 0; c < 8; c++) {
            l[hh][c] = __expf(l[hh][c] - mx[hh]);
            s += l[hh][c];
        }
        #pragma unroll
        for (int o = 16; o > 0; o >>= 1)
            s += __shfl_xor_sync(0xffffffffu, s, o);
        if (lane == 0) redsm[(hb + hh) * 4 + (w & 3)] = s;
    }
    __syncthreads();
    #pragma unroll
    for (int hh = 0; hh < 4; hh++) {
        const float* p = redsm + (hb + hh) * 4;
        const float rinv = 1.0f / (p[0] + p[1] + p[2] + p[3]);
        float* arow = attn + (((size_t)b * H_ + hb + hh) * S_ + i) * S_;
        #pragma unroll
        for (int c = 0; c < 8; c++)
            arow[c * K2_CHUNK + jl] = l[hh][c] * rinv;
    }
}

// ---------------------------------------------------------------------------
// K3 (8x4 micro, crossbar-optimal like K1): output = attn @ v via g_vt.
// Tile 64i x 64n, 128 threads (tx: 16 n-slots, ty: 8 i-octets), pitch 66,
// j chunks of 64, 2-deep cp8 ring, 3 CTAs/SM. Per jp: 12 LDS.64 / 32 FMA2.
// ---------------------------------------------------------------------------
static constexpr int K3_PITCH = 66;
static constexpr int K3_BUF = 64 * K3_PITCH;                  // 4224 floats
static constexpr int K3_SMEM = 4 * K3_BUF * 4;                // 67584 B

__device__ __forceinline__ void k3_stage(uint32_t as_u, uint32_t vs_u,
                                         const float* __restrict__ ab,
                                         const float* __restrict__ vtb,
                                         int jc, int t)
{
    #pragma unroll
    for (int m = 0; m < 16; m++) {
        const int idx = m * 128 + t;
        const int row = idx >> 5, p = idx & 31;
        cp8(as_u + (uint32_t)(row * K3_PITCH + 2 * p) * 4u,
            ab + (size_t)row * S_ + jc + 2 * p);
    }
    #pragma unroll
    for (int m = 0; m < 16; m++) {
        const int idx = m * 128 + t;
        const int row = idx >> 5, p = idx & 31;
        cp8(vs_u + (uint32_t)(row * K3_PITCH + 2 * p) * 4u,
            vtb + (size_t)row * S_ + jc + 2 * p);
    }
    CP_COMMIT();
}

__global__ void __launch_bounds__(128, 3) k3_av(const float* __restrict__ attn,
                                                float* __restrict__ out)
{
    extern __shared__ float sm3[];
    // ring layout: [As0][Vs0][As1][Vs1]
    float* Asb[2] = { sm3,              sm3 + 2 * K3_BUF };
    float* Vsb[2] = { sm3 + K3_BUF,     sm3 + 3 * K3_BUF };

    const int bh = blockIdx.y;
    const int i0 = blockIdx.x * 64;
    const int t = threadIdx.x;
    const int tx = t & 15;       // n slots: tx + 16s
    const int ty = t >> 4;       // 0..7 -> i rows ty*8 + r
    const float* ab = attn + ((size_t)bh * S_ + i0) * S_;
    const float* vtb = g_vt + (size_t)bh * DV_ * S_;
    const uint32_t as_u[2] = { s2u(Asb[0]), s2u(Asb[1]) };
    const uint32_t vs_u[2] = { s2u(Vsb[0]), s2u(Vsb[1]) };

    unsigned long long acc[8][4] = {};   // [i-row r][n-slot s], packed (ej, oj)

    k3_stage(as_u[0], vs_u[0], ab, vtb, 0, t);

    for (int c = 0; c < 16; c++) {
        if (c) __syncthreads();          // readers of buf (c+1)&1 (iter c-1) done
        if (c < 15) {
            k3_stage(as_u[(c + 1) & 1], vs_u[(c + 1) & 1], ab, vtb, (c + 1) * 64, t);
            CP_WAIT1();
        } else {
            CP_WAIT0();
        }
        __syncthreads();                 // buf c&1 visible to all

        const float* ap = Asb[c & 1] + (ty * 8) * K3_PITCH;
        const float* vp = Vsb[c & 1] + tx * K3_PITCH;
        #pragma unroll 8
        for (int jp = 0; jp < 32; jp++) {
            unsigned long long vv[4], av[8];
            #pragma unroll
            for (int s = 0; s < 4; s++)
                vv[s] = *(const unsigned long long*)(vp + (16 * s) * K3_PITCH + 2 * jp);
            #pragma unroll
            for (int r = 0; r < 8; r++)
                av[r] = *(const unsigned long long*)(ap + r * K3_PITCH + 2 * jp);
            #pragma unroll
            for (int r = 0; r < 8; r++)
                #pragma unroll
                for (int s = 0; s < 4; s++)
                    FMA2(acc[r][s], av[r], vv[s]);
        }
    }

    #pragma unroll
    for (int r = 0; r < 8; r++) {
        float* orow = out + ((size_t)bh * S_ + i0 + ty * 8 + r) * DV_;
        #pragma unroll
        for (int s = 0; s < 4; s++) {
            float2 pv = unpack2(acc[r][s]);
            orow[tx + 16 * s] = pv.x + pv.y;
        }
    }
}

// ---------------------------------------------------------------------------
extern "C" void kernel_launch(void* const* d_in, const int* in_sizes, int n_in,
                              void* d_out, int out_size)
{
    const float* q    = (const float*)d_in[0];
    const float* k    = (const float*)d_in[1];
    const float* v    = (const float*)d_in[2];
    const int*   mask = (const int*)d_in[3];
    const float* rpr  = (const float*)d_in[4];
    float* out  = (float*)d_out;
    float* attn = out + OUT_ATTN_OFF;

    cudaFuncSetAttribute(k1_qk, cudaFuncAttributeMaxDynamicSharedMemorySize, K1_SMEM);
    cudaFuncSetAttribute(k2_rpr_softmax, cudaFuncAttributeMaxDynamicSharedMemorySize,
                         K2_SMEM);
    cudaFuncSetAttribute(k3_av, cudaFuncAttributeMaxDynamicSharedMemorySize, K3_SMEM);

    {   // launch 0 — K1: attn1 logits into attn region
        dim3 grid(S_ / 64, S_ / 128, B_ * H_);
        k1_qk<<<grid, 256, K1_SMEM>>>(q, k, attn);
    }
    {   // launch 1 — K0t: transpose v into g_vt (independent of K1)
        dim3 grid(S_ / 64, B_ * H_);
        k0_vt<<<grid, 256>>>(v);
    }
    {   // launch 2 — K2: + positional term, mask, softmax
        dim3 grid(S_, B_);
        k2_rpr_softmax<<<grid, 256, K2_SMEM>>>(q, rpr, mask, attn);
    }
    {   // launch 3 (profiled) — K3: output = attn @ v
        dim3 grid(S_ / 64, B_ * H_);
        k3_av<<<grid, 128, K3_SMEM>>>(attn, out);
    }
}

// round 16
// speedup vs baseline: 1.0731x; 1.0048x over previous
#include <cuda_runtime.h>
#include <cstdint>

#define B_ 2
#define H_ 8
#define S_ 1024
#define DK_ 64
#define DV_ 64
static constexpr float INV_T = 0.125f;                   // 1/temperature
static constexpr int OUT_ATTN_OFF = B_ * H_ * S_ * DV_;  // 1048576

// 4 MB transposed-V scratch: g_vt[bh][n][j] = v[bh][j][n]
__device__ float g_vt[B_ * H_ * DV_ * S_];
// 4 MB partial-output scratch for K3 j-split 1
__device__ float g_part[B_ * H_ * S_ * DV_];

// ---- packed fp32 helpers (sm_103a f32x2 pipe) -------------------------------
#define FMA2(acc, a, b) asm("fma.rn.f32x2 %0, %1, %2, %0;" : "+l"(acc) : "l"(a), "l"(b))

__device__ __forceinline__ float2 unpack2(unsigned long long v) {
    float2 r;
    asm("mov.b64 {%0, %1}, %2;" : "=f"(r.x), "=f"(r.y) : "l"(v));
    return r;
}

// ---- cp.async helpers -------------------------------------------------------
__device__ __forceinline__ uint32_t s2u(const void* p) {
    return (uint32_t)__cvta_generic_to_shared(p);
}
__device__ __forceinline__ void cp8(uint32_t dst, const void* src) {
    asm volatile("cp.async.ca.shared.global [%0], [%1], 8;" :: "r"(dst), "l"(src));
}
__device__ __forceinline__ void cp16(uint32_t dst, const void* src) {
    asm volatile("cp.async.cg.shared.global [%0], [%1], 16;" :: "r"(dst), "l"(src));
}
#define CP_COMMIT() asm volatile("cp.async.commit_group;")
#define CP_WAIT0()  asm volatile("cp.async.wait_group 0;")
#define CP_WAIT1()  asm volatile("cp.async.wait_group 1;")
#define CP_WAIT2()  asm volatile("cp.async.wait_group 2;")

// ---------------------------------------------------------------------------
// K1 (measured 50us, UNCHANGED): attn1 = (q/T).k^T, d-parity packing.
// Tile 128i x 64j, 256 threads, 8x4 micro (j strided by 16), pitch 66.
// ---------------------------------------------------------------------------
static constexpr int K1_PITCH = 66;
static constexpr int K1_SMEM = (128 + 64) * K1_PITCH * 4;   // 50688 B

__global__ void __launch_bounds__(256, 2) k1_qk(const float* __restrict__ q,
                                                const float* __restrict__ k,
                                                float* __restrict__ attn)
{
    extern __shared__ float sm1[];
    float* Qs = sm1;                    // [128][66]
    float* Ks = sm1 + 128 * K1_PITCH;   // [64][66]

    const int bh = blockIdx.z;
    const int i0 = blockIdx.y * 128;
    const int j0 = blockIdx.x * 64;
    const float* qb = q + ((size_t)bh * S_ + i0) * DK_;
    const float* kb = k + ((size_t)bh * S_ + j0) * DK_;
    const int t = threadIdx.x;
    const uint32_t qs_u = s2u(Qs), ks_u = s2u(Ks);

    #pragma unroll
    for (int m = 0; m < 16; m++) {
        const int idx = m * 256 + t;
        const int row = idx >> 5, p = idx & 31;
        cp8(qs_u + (uint32_t)(row * K1_PITCH + 2 * p) * 4u, qb + (size_t)idx * 2);
    }
    #pragma unroll
    for (int m = 0; m < 8; m++) {
        const int idx = m * 256 + t;
        const int row = idx >> 5, p = idx & 31;
        cp8(ks_u + (uint32_t)(row * K1_PITCH + 2 * p) * 4u, kb + (size_t)idx * 2);
    }
    CP_COMMIT();
    CP_WAIT0();
    __syncthreads();

    const int tx = t & 15;
    const int ty = t >> 4;
    const float* qp = Qs + (ty * 8) * K1_PITCH;
    const float* kp = Ks + tx * K1_PITCH;

    unsigned long long acc[8][4] = {};

    #pragma unroll 8
    for (int dp = 0; dp < 32; dp++) {
        unsigned long long kv[4], qv[8];
        #pragma unroll
        for (int s = 0; s < 4; s++)
            kv[s] = *(const unsigned long long*)(kp + (16 * s) * K1_PITCH + 2 * dp);
        #pragma unroll
        for (int r = 0; r < 8; r++)
            qv[r] = *(const unsigned long long*)(qp + r * K1_PITCH + 2 * dp);
        #pragma unroll
        for (int r = 0; r < 8; r++)
            #pragma unroll
            for (int s = 0; s < 4; s++)
                FMA2(acc[r][s], qv[r], kv[s]);
    }

    #pragma unroll
    for (int r = 0; r < 8; r++) {
        float* row = attn + (((size_t)bh * S_ + i0 + ty * 8 + r) * S_) + j0;
        #pragma unroll
        for (int s = 0; s < 4; s++) {
            float2 pv = unpack2(acc[r][s]);
            row[tx + 16 * s] = (pv.x + pv.y) * INV_T;
        }
    }
}

// ---------------------------------------------------------------------------
// K0t: one-time transpose v -> g_vt[bh][n][j]. 64j x 64n tiles.
// ---------------------------------------------------------------------------
__global__ void __launch_bounds__(256) k0_vt(const float* __restrict__ v)
{
    __shared__ float ts[64][65];
    const int j0 = blockIdx.x * 64;
    const int bh = blockIdx.y;
    const int t = threadIdx.x;
    const float* vb = v + (size_t)bh * S_ * DV_;

    #pragma unroll
    for (int m = 0; m < 4; m++) {
        const int idx = m * 256 + t;
        const int row = idx >> 4, g = idx & 15;
        float4 a = *(const float4*)(vb + (size_t)(j0 + row) * DV_ + 4 * g);
        ts[row][4 * g + 0] = a.x;
        ts[row][4 * g + 1] = a.y;
        ts[row][4 * g + 2] = a.z;
        ts[row][4 * g + 3] = a.w;
    }
    __syncthreads();

    float* dst = g_vt + (size_t)bh * DV_ * S_;
    #pragma unroll
    for (int m = 0; m < 4; m++) {
        const int idx = m * 256 + t;
        const int n = idx >> 4, jq = idx & 15;
        float4 w = make_float4(ts[4 * jq + 0][n], ts[4 * jq + 1][n],
                               ts[4 * jq + 2][n], ts[4 * jq + 3][n]);
        *(float4*)(dst + (size_t)n * S_ + j0 + 4 * jq) = w;
    }
}

// ---------------------------------------------------------------------------
// K2 (measured 137us, UNCHANGED): logits = attn1 + qs.rpr; mask; softmax.
// Head-group 4, chunk 128 j, d-parity, 3-buffer cp16 ring, 2 CTAs/SM.
// ---------------------------------------------------------------------------
static constexpr int K2_CHUNK = 128;
static constexpr int K2_PITCH = 68;                      // 16B-aligned rows
static constexpr int K2_BUF = K2_CHUNK * K2_PITCH;       // 8704 floats
static constexpr int K2_SMEM = (576 + 3 * K2_BUF) * 4;   // 106752 B

__device__ __forceinline__ void k2_stage(uint32_t rs_u, const float* __restrict__ src,
                                         int t)
{
    #pragma unroll
    for (int m = 0; m < 8; m++) {
        const int idx = m * 256 + t;
        const int row = idx >> 4;
        const int gg  = idx & 15;
        cp16(rs_u + (uint32_t)(row * K2_PITCH + 4 * gg) * 4u, src + (size_t)idx * 4);
    }
    CP_COMMIT();
}

__global__ void __launch_bounds__(256, 2) k2_rpr_softmax(
    const float* __restrict__ q,
    const float* __restrict__ rpr,
    const int* __restrict__ mask,
    float* __restrict__ attn)
{
    extern __shared__ float sm2[];
    float* qs3   = sm2;             // [32 dp][8 h][2 e] = 512
    float* redmx = sm2 + 512;       // [8 h][4 warps]
    float* redsm = sm2 + 544;       // [8 h][4 warps]
    float* bufs  = sm2 + 576;       // 3 x [128][68]

    const int b = blockIdx.y;
    const int i = blockIdx.x;
    const int t = threadIdx.x;
    const int g = t >> 7;           // head group: heads g*4 .. g*4+3
    const int hb = g * 4;
    const int jl = t & 127;
    const int w = t >> 5, lane = t & 31;

    const float* rbase = rpr + ((size_t)b * S_ + i) * S_ * DK_;
    const int* mrow = mask + ((size_t)b * S_ + i) * S_;
    uint32_t ru[3];
    const float* rp2[3];
    #pragma unroll
    for (int n = 0; n < 3; n++) {
        rp2[n] = bufs + n * K2_BUF;
        ru[n] = s2u(rp2[n]);
    }

    k2_stage(ru[0], rbase, t);
    k2_stage(ru[1], rbase + (size_t)K2_CHUNK * DK_, t);

    #pragma unroll
    for (int idx = t; idx < 512; idx += 256) {
        const int e = idx & 1, h = (idx >> 1) & 7, dp = idx >> 4;
        qs3[idx] = q[(((size_t)b * H_ + h) * S_ + i) * DK_ + 2 * dp + e] * INV_T;
    }

    float l[4][8];                  // [head-in-group][chunk]

    #pragma unroll
    for (int c = 0; c < 8; c++) {
        if (c) __syncthreads();

        const int j = c * K2_CHUNK + jl;
        const int mk = mrow[j];
        float a1v[4];
        #pragma unroll
        for (int hh = 0; hh < 4; hh++)
            a1v[hh] = attn[(((size_t)b * H_ + hb + hh) * S_ + i) * S_ + j];

        if (c < 6) {
            k2_stage(ru[(c + 2) % 3], rbase + (size_t)(c + 2) * K2_CHUNK * DK_, t);
            CP_WAIT2();
        } else if (c == 6) {
            CP_WAIT1();
        } else {
            CP_WAIT0();
        }
        __syncthreads();

        unsigned long long acc[4] = {};
        const float* rr = rp2[c % 3] + jl * K2_PITCH;
        #pragma unroll
        for (int gg = 0; gg < 16; gg++) {
            ulonglong2 rpv = *(const ulonglong2*)(rr + 4 * gg);
            const float* qb0 = qs3 + (2 * gg) * 16 + hb * 2;
            ulonglong2 qA = *(const ulonglong2*)(qb0);
            ulonglong2 qB = *(const ulonglong2*)(qb0 + 4);
            ulonglong2 qC = *(const ulonglong2*)(qb0 + 16);
            ulonglong2 qD = *(const ulonglong2*)(qb0 + 20);
            FMA2(acc[0], qA.x, rpv.x);
            FMA2(acc[1], qA.y, rpv.x);
            FMA2(acc[2], qB.x, rpv.x);
            FMA2(acc[3], qB.y, rpv.x);
            FMA2(acc[0], qC.x, rpv.y);
            FMA2(acc[1], qC.y, rpv.y);
            FMA2(acc[2], qD.x, rpv.y);
            FMA2(acc[3], qD.y, rpv.y);
        }
        #pragma unroll
        for (int hh = 0; hh < 4; hh++) {
            float2 pv = unpack2(acc[hh]);
            l[hh][c] = mk ? (pv.x + pv.y + a1v[hh]) : -1e9f;
        }
    }

    // ---- block softmax ----
    #pragma unroll
    for (int hh = 0; hh < 4; hh++) {
        float m = l[hh][0];
        #pragma unroll
        for (int c = 1; c < 8; c++) m = fmaxf(m, l[hh][c]);
        #pragma unroll
        for (int o = 16; o > 0; o >>= 1)
            m = fmaxf(m, __shfl_xor_sync(0xffffffffu, m, o));
        if (lane == 0) redmx[(hb + hh) * 4 + (w & 3)] = m;
    }
    __syncthreads();
    float mx[4];
    #pragma unroll
    for (int hh = 0; hh < 4; hh++) {
        const float* p = redmx + (hb + hh) * 4;
        mx[hh] = fmaxf(fmaxf(p[0], p[1]), fmaxf(p[2], p[3]));
    }
    #pragma unroll
    for (int hh = 0; hh < 4; hh++) {
        float s = 0.f;
        #pragma unroll
        for (int c = 0; c < 8; c++) {
            l[hh][c] = __expf(l[hh][c] - mx[hh]);
            s += l[hh][c];
        }
        #pragma unroll
        for (int o = 16; o > 0; o >>= 1)
            s += __shfl_xor_sync(0xffffffffu, s, o);
        if (lane == 0) redsm[(hb + hh) * 4 + (w & 3)] = s;
    }
    __syncthreads();
    #pragma unroll
    for (int hh = 0; hh < 4; hh++) {
        const float* p = redsm + (hb + hh) * 4;
        const float rinv = 1.0f / (p[0] + p[1] + p[2] + p[3]);
        float* arow = attn + (((size_t)b * H_ + hb + hh) * S_ + i) * S_;
        #pragma unroll
        for (int c = 0; c < 8; c++)
            arow[c * K2_CHUNK + jl] = l[hh][c] * rinv;
    }
}

// ---------------------------------------------------------------------------
// K3 (8x4 micro + j-SPLIT for occupancy): output = attn @ v via g_vt.
// blockIdx.z = j-split (0: j<512 -> out, 1: j>=512 -> g_part). Grid 512.
// Tile 64i x 64n, 128 threads, pitch 66, 8 chunks of 64 j, 2-deep cp8 ring.
// ---------------------------------------------------------------------------
static constexpr int K3_PITCH = 66;
static constexpr int K3_BUF = 64 * K3_PITCH;                  // 4224 floats
static constexpr int K3_SMEM = 4 * K3_BUF * 4;                // 67584 B

__device__ __forceinline__ void k3_stage(uint32_t as_u, uint32_t vs_u,
                                         const float* __restrict__ ab,
                                         const float* __restrict__ vtb,
                                         int jc, int t)
{
    #pragma unroll
    for (int m = 0; m < 16; m++) {
        const int idx = m * 128 + t;
        const int row = idx >> 5, p = idx & 31;
        cp8(as_u + (uint32_t)(row * K3_PITCH + 2 * p) * 4u,
            ab + (size_t)row * S_ + jc + 2 * p);
    }
    #pragma unroll
    for (int m = 0; m < 16; m++) {
        const int idx = m * 128 + t;
        const int row = idx >> 5, p = idx & 31;
        cp8(vs_u + (uint32_t)(row * K3_PITCH + 2 * p) * 4u,
            vtb + (size_t)row * S_ + jc + 2 * p);
    }
    CP_COMMIT();
}

__global__ void __launch_bounds__(128, 3) k3_av(const float* __restrict__ attn,
                                                float* __restrict__ out)
{
    extern __shared__ float sm3[];
    // ring layout: [As0][Vs0][As1][Vs1]
    float* Asb[2] = { sm3,              sm3 + 2 * K3_BUF };
    float* Vsb[2] = { sm3 + K3_BUF,     sm3 + 3 * K3_BUF };

    const int bh = blockIdx.y;
    const int i0 = blockIdx.x * 64;
    const int js = blockIdx.z;           // j-split: 0 or 1
    const int jb = js * 512;
    const int t = threadIdx.x;
    const int tx = t & 15;       // n slots: tx + 16s
    const int ty = t >> 4;       // 0..7 -> i rows ty*8 + r
    const float* ab = attn + ((size_t)bh * S_ + i0) * S_;
    const float* vtb = g_vt + (size_t)bh * DV_ * S_;
    float* dst = (js == 0) ? out : g_part;
    const uint32_t as_u[2] = { s2u(Asb[0]), s2u(Asb[1]) };
    const uint32_t vs_u[2] = { s2u(Vsb[0]), s2u(Vsb[1]) };

    unsigned long long acc[8][4] = {};   // [i-row r][n-slot s], packed (ej, oj)

    k3_stage(as_u[0], vs_u[0], ab, vtb, jb, t);

    for (int c = 0; c < 8; c++) {
        if (c) __syncthreads();          // readers of buf (c+1)&1 (iter c-1) done
        if (c < 7) {
            k3_stage(as_u[(c + 1) & 1], vs_u[(c + 1) & 1], ab, vtb,
                     jb + (c + 1) * 64, t);
            CP_WAIT1();
        } else {
            CP_WAIT0();
        }
        __syncthreads();                 // buf c&1 visible to all

        const float* ap = Asb[c & 1] + (ty * 8) * K3_PITCH;
        const float* vp = Vsb[c & 1] + tx * K3_PITCH;
        #pragma unroll 8
        for (int jp = 0; jp < 32; jp++) {
            unsigned long long vv[4], av[8];
            #pragma unroll
            for (int s = 0; s < 4; s++)
                vv[s] = *(const unsigned long long*)(vp + (16 * s) * K3_PITCH + 2 * jp);
            #pragma unroll
            for (int r = 0; r < 8; r++)
                av[r] = *(const unsigned long long*)(ap + r * K3_PITCH + 2 * jp);
            #pragma unroll
            for (int r = 0; r < 8; r++)
                #pragma unroll
                for (int s = 0; s < 4; s++)
                    FMA2(acc[r][s], av[r], vv[s]);
        }
    }

    #pragma unroll
    for (int r = 0; r < 8; r++) {
        float* orow = dst + ((size_t)bh * S_ + i0 + ty * 8 + r) * DV_;
        #pragma unroll
        for (int s = 0; s < 4; s++) {
            float2 pv = unpack2(acc[r][s]);
            orow[tx + 16 * s] = pv.x + pv.y;
        }
    }
}

// ---------------------------------------------------------------------------
// K3r: out += g_part (j-split reduction). 1M floats, float4.
// ---------------------------------------------------------------------------
__global__ void __launch_bounds__(256) k3_red(float* __restrict__ out)
{
    const int idx = blockIdx.x * 256 + threadIdx.x;
    float4 a = *(const float4*)(out + (size_t)idx * 4);
    float4 b = *(const float4*)(g_part + (size_t)idx * 4);
    a.x += b.x; a.y += b.y; a.z += b.z; a.w += b.w;
    *(float4*)(out + (size_t)idx * 4) = a;
}

// ---------------------------------------------------------------------------
extern "C" void kernel_launch(void* const* d_in, const int* in_sizes, int n_in,
                              void* d_out, int out_size)
{
    const float* q    = (const float*)d_in[0];
    const float* k    = (const float*)d_in[1];
    const float* v    = (const float*)d_in[2];
    const int*   mask = (const int*)d_in[3];
    const float* rpr  = (const float*)d_in[4];
    float* out  = (float*)d_out;
    float* attn = out + OUT_ATTN_OFF;

    cudaFuncSetAttribute(k1_qk, cudaFuncAttributeMaxDynamicSharedMemorySize, K1_SMEM);
    cudaFuncSetAttribute(k2_rpr_softmax, cudaFuncAttributeMaxDynamicSharedMemorySize,
                         K2_SMEM);
    cudaFuncSetAttribute(k3_av, cudaFuncAttributeMaxDynamicSharedMemorySize, K3_SMEM);

    {   // launch 0 — K1: attn1 logits into attn region
        dim3 grid(S_ / 64, S_ / 128, B_ * H_);
        k1_qk<<<grid, 256, K1_SMEM>>>(q, k, attn);
    }
    {   // launch 1 — K0t: transpose v into g_vt (independent of K1)
        dim3 grid(S_ / 64, B_ * H_);
        k0_vt<<<grid, 256>>>(v);
    }
    {   // launch 2 — K2: + positional term, mask, softmax
        dim3 grid(S_, B_);
        k2_rpr_softmax<<<grid, 256, K2_SMEM>>>(q, rpr, mask, attn);
    }
    {   // launch 3 (profiled) — K3: output partials = attn @ v (j-split)
        dim3 grid(S_ / 64, B_ * H_, 2);
        k3_av<<<grid, 128, K3_SMEM>>>(attn, out);
    }
    {   // launch 4 — K3r: out += g_part
        k3_red<<<(B_ * H_ * S_ * DV_ / 4) / 256, 256>>>(out);
    }
}

// round 17
// speedup vs baseline: 1.2149x; 1.1321x over previous
#include <cuda_runtime.h>
#include <cstdint>

#define B_ 2
#define H_ 8
#define S_ 1024
#define DK_ 64
#define DV_ 64
static constexpr float INV_T = 0.125f;                   // 1/temperature
static constexpr int OUT_ATTN_OFF = B_ * H_ * S_ * DV_;  // 1048576

// 4 MB transposed-V scratch: g_vt[bh][n][j] = v[bh][j][n]
__device__ float g_vt[B_ * H_ * DV_ * S_];

// ---- packed fp32 helpers (sm_103a f32x2 pipe) -------------------------------
#define FMA2(acc, a, b) asm("fma.rn.f32x2 %0, %1, %2, %0;" : "+l"(acc) : "l"(a), "l"(b))

__device__ __forceinline__ float2 unpack2(unsigned long long v) {
    float2 r;
    asm("mov.b64 {%0, %1}, %2;" : "=f"(r.x), "=f"(r.y) : "l"(v));
    return r;
}

// ---- cp.async helpers -------------------------------------------------------
__device__ __forceinline__ uint32_t s2u(const void* p) {
    return (uint32_t)__cvta_generic_to_shared(p);
}
__device__ __forceinline__ void cp8(uint32_t dst, const void* src) {
    asm volatile("cp.async.ca.shared.global [%0], [%1], 8;" :: "r"(dst), "l"(src));
}
__device__ __forceinline__ void cp16(uint32_t dst, const void* src) {
    asm volatile("cp.async.cg.shared.global [%0], [%1], 16;" :: "r"(dst), "l"(src));
}
#define CP_COMMIT() asm volatile("cp.async.commit_group;")
#define CP_WAIT0()  asm volatile("cp.async.wait_group 0;")
#define CP_WAIT1()  asm volatile("cp.async.wait_group 1;")
#define CP_WAIT2()  asm volatile("cp.async.wait_group 2;")

// ---------------------------------------------------------------------------
// K1 (measured 50us, UNCHANGED): attn1 = (q/T).k^T, d-parity packing.
// Tile 128i x 64j, 256 threads, 8x4 micro (j strided by 16), pitch 66.
// ---------------------------------------------------------------------------
static constexpr int K1_PITCH = 66;
static constexpr int K1_SMEM = (128 + 64) * K1_PITCH * 4;   // 50688 B

__global__ void __launch_bounds__(256, 2) k1_qk(const float* __restrict__ q,
                                                const float* __restrict__ k,
                                                float* __restrict__ attn)
{
    extern __shared__ float sm1[];
    float* Qs = sm1;                    // [128][66]
    float* Ks = sm1 + 128 * K1_PITCH;   // [64][66]

    const int bh = blockIdx.z;
    const int i0 = blockIdx.y * 128;
    const int j0 = blockIdx.x * 64;
    const float* qb = q + ((size_t)bh * S_ + i0) * DK_;
    const float* kb = k + ((size_t)bh * S_ + j0) * DK_;
    const int t = threadIdx.x;
    const uint32_t qs_u = s2u(Qs), ks_u = s2u(Ks);

    #pragma unroll
    for (int m = 0; m < 16; m++) {
        const int idx = m * 256 + t;
        const int row = idx >> 5, p = idx & 31;
        cp8(qs_u + (uint32_t)(row * K1_PITCH + 2 * p) * 4u, qb + (size_t)idx * 2);
    }
    #pragma unroll
    for (int m = 0; m < 8; m++) {
        const int idx = m * 256 + t;
        const int row = idx >> 5, p = idx & 31;
        cp8(ks_u + (uint32_t)(row * K1_PITCH + 2 * p) * 4u, kb + (size_t)idx * 2);
    }
    CP_COMMIT();
    CP_WAIT0();
    __syncthreads();

    const int tx = t & 15;
    const int ty = t >> 4;
    const float* qp = Qs + (ty * 8) * K1_PITCH;
    const float* kp = Ks + tx * K1_PITCH;

    unsigned long long acc[8][4] = {};

    #pragma unroll 8
    for (int dp = 0; dp < 32; dp++) {
        unsigned long long kv[4], qv[8];
        #pragma unroll
        for (int s = 0; s < 4; s++)
            kv[s] = *(const unsigned long long*)(kp + (16 * s) * K1_PITCH + 2 * dp);
        #pragma unroll
        for (int r = 0; r < 8; r++)
            qv[r] = *(const unsigned long long*)(qp + r * K1_PITCH + 2 * dp);
        #pragma unroll
        for (int r = 0; r < 8; r++)
            #pragma unroll
            for (int s = 0; s < 4; s++)
                FMA2(acc[r][s], qv[r], kv[s]);
    }

    #pragma unroll
    for (int r = 0; r < 8; r++) {
        float* row = attn + (((size_t)bh * S_ + i0 + ty * 8 + r) * S_) + j0;
        #pragma unroll
        for (int s = 0; s < 4; s++) {
            float2 pv = unpack2(acc[r][s]);
            row[tx + 16 * s] = (pv.x + pv.y) * INV_T;
        }
    }
}

// ---------------------------------------------------------------------------
// K0t: one-time transpose v -> g_vt[bh][n][j], PLUS zero-init of out
// (required by K3's atomicAdd epilogue). 64j x 64n tiles, grid (16,16).
// ---------------------------------------------------------------------------
__global__ void __launch_bounds__(256) k0_vt(const float* __restrict__ v,
                                             float* __restrict__ out)
{
    __shared__ float ts[64][65];
    const int j0 = blockIdx.x * 64;
    const int bh = blockIdx.y;
    const int t = threadIdx.x;
    const float* vb = v + (size_t)bh * S_ * DV_;

    // zero 4096 floats of out per CTA (256 CTAs x 4096 = 1M floats)
    {
        const size_t base = ((size_t)(blockIdx.y * 16 + blockIdx.x) * 4096) + t * 16;
        float4 z = make_float4(0.f, 0.f, 0.f, 0.f);
        *(float4*)(out + base)      = z;
        *(float4*)(out + base + 4)  = z;
        *(float4*)(out + base + 8)  = z;
        *(float4*)(out + base + 12) = z;
    }

    #pragma unroll
    for (int m = 0; m < 4; m++) {
        const int idx = m * 256 + t;
        const int row = idx >> 4, g = idx & 15;
        float4 a = *(const float4*)(vb + (size_t)(j0 + row) * DV_ + 4 * g);
        ts[row][4 * g + 0] = a.x;
        ts[row][4 * g + 1] = a.y;
        ts[row][4 * g + 2] = a.z;
        ts[row][4 * g + 3] = a.w;
    }
    __syncthreads();

    float* dst = g_vt + (size_t)bh * DV_ * S_;
    #pragma unroll
    for (int m = 0; m < 4; m++) {
        const int idx = m * 256 + t;
        const int n = idx >> 4, jq = idx & 15;
        float4 w = make_float4(ts[4 * jq + 0][n], ts[4 * jq + 1][n],
                               ts[4 * jq + 2][n], ts[4 * jq + 3][n]);
        *(float4*)(dst + (size_t)n * S_ + j0 + 4 * jq) = w;
    }
}

// ---------------------------------------------------------------------------
// K2 (measured 137us, UNCHANGED): logits = attn1 + qs.rpr; mask; softmax.
// Head-group 4, chunk 128 j, d-parity, 3-buffer cp16 ring, 2 CTAs/SM.
// ---------------------------------------------------------------------------
static constexpr int K2_CHUNK = 128;
static constexpr int K2_PITCH = 68;                      // 16B-aligned rows
static constexpr int K2_BUF = K2_CHUNK * K2_PITCH;       // 8704 floats
static constexpr int K2_SMEM = (576 + 3 * K2_BUF) * 4;   // 106752 B

__device__ __forceinline__ void k2_stage(uint32_t rs_u, const float* __restrict__ src,
                                         int t)
{
    #pragma unroll
    for (int m = 0; m < 8; m++) {
        const int idx = m * 256 + t;
        const int row = idx >> 4;
        const int gg  = idx & 15;
        cp16(rs_u + (uint32_t)(row * K2_PITCH + 4 * gg) * 4u, src + (size_t)idx * 4);
    }
    CP_COMMIT();
}

__global__ void __launch_bounds__(256, 2) k2_rpr_softmax(
    const float* __restrict__ q,
    const float* __restrict__ rpr,
    const int* __restrict__ mask,
    float* __restrict__ attn)
{
    extern __shared__ float sm2[];
    float* qs3   = sm2;             // [32 dp][8 h][2 e] = 512
    float* redmx = sm2 + 512;       // [8 h][4 warps]
    float* redsm = sm2 + 544;       // [8 h][4 warps]
    float* bufs  = sm2 + 576;       // 3 x [128][68]

    const int b = blockIdx.y;
    const int i = blockIdx.x;
    const int t = threadIdx.x;
    const int g = t >> 7;           // head group: heads g*4 .. g*4+3
    const int hb = g * 4;
    const int jl = t & 127;
    const int w = t >> 5, lane = t & 31;

    const float* rbase = rpr + ((size_t)b * S_ + i) * S_ * DK_;
    const int* mrow = mask + ((size_t)b * S_ + i) * S_;
    uint32_t ru[3];
    const float* rp2[3];
    #pragma unroll
    for (int n = 0; n < 3; n++) {
        rp2[n] = bufs + n * K2_BUF;
        ru[n] = s2u(rp2[n]);
    }

    k2_stage(ru[0], rbase, t);
    k2_stage(ru[1], rbase + (size_t)K2_CHUNK * DK_, t);

    #pragma unroll
    for (int idx = t; idx < 512; idx += 256) {
        const int e = idx & 1, h = (idx >> 1) & 7, dp = idx >> 4;
        qs3[idx] = q[(((size_t)b * H_ + h) * S_ + i) * DK_ + 2 * dp + e] * INV_T;
    }

    float l[4][8];                  // [head-in-group][chunk]

    #pragma unroll
    for (int c = 0; c < 8; c++) {
        if (c) __syncthreads();

        const int j = c * K2_CHUNK + jl;
        const int mk = mrow[j];
        float a1v[4];
        #pragma unroll
        for (int hh = 0; hh < 4; hh++)
            a1v[hh] = attn[(((size_t)b * H_ + hb + hh) * S_ + i) * S_ + j];

        if (c < 6) {
            k2_stage(ru[(c + 2) % 3], rbase + (size_t)(c + 2) * K2_CHUNK * DK_, t);
            CP_WAIT2();
        } else if (c == 6) {
            CP_WAIT1();
        } else {
            CP_WAIT0();
        }
        __syncthreads();

        unsigned long long acc[4] = {};
        const float* rr = rp2[c % 3] + jl * K2_PITCH;
        #pragma unroll
        for (int gg = 0; gg < 16; gg++) {
            ulonglong2 rpv = *(const ulonglong2*)(rr + 4 * gg);
            const float* qb0 = qs3 + (2 * gg) * 16 + hb * 2;
            ulonglong2 qA = *(const ulonglong2*)(qb0);
            ulonglong2 qB = *(const ulonglong2*)(qb0 + 4);
            ulonglong2 qC = *(const ulonglong2*)(qb0 + 16);
            ulonglong2 qD = *(const ulonglong2*)(qb0 + 20);
            FMA2(acc[0], qA.x, rpv.x);
            FMA2(acc[1], qA.y, rpv.x);
            FMA2(acc[2], qB.x, rpv.x);
            FMA2(acc[3], qB.y, rpv.x);
            FMA2(acc[0], qC.x, rpv.y);
            FMA2(acc[1], qC.y, rpv.y);
            FMA2(acc[2], qD.x, rpv.y);
            FMA2(acc[3], qD.y, rpv.y);
        }
        #pragma unroll
        for (int hh = 0; hh < 4; hh++) {
            float2 pv = unpack2(acc[hh]);
            l[hh][c] = mk ? (pv.x + pv.y + a1v[hh]) : -1e9f;
        }
    }

    // ---- block softmax ----
    #pragma unroll
    for (int hh = 0; hh < 4; hh++) {
        float m = l[hh][0];
        #pragma unroll
        for (int c = 1; c < 8; c++) m = fmaxf(m, l[hh][c]);
        #pragma unroll
        for (int o = 16; o > 0; o >>= 1)
            m = fmaxf(m, __shfl_xor_sync(0xffffffffu, m, o));
        if (lane == 0) redmx[(hb + hh) * 4 + (w & 3)] = m;
    }
    __syncthreads();
    float mx[4];
    #pragma unroll
    for (int hh = 0; hh < 4; hh++) {
        const float* p = redmx + (hb + hh) * 4;
        mx[hh] = fmaxf(fmaxf(p[0], p[1]), fmaxf(p[2], p[3]));
    }
    #pragma unroll
    for (int hh = 0; hh < 4; hh++) {
        float s = 0.f;
        #pragma unroll
        for (int c = 0; c < 8; c++) {
            l[hh][c] = __expf(l[hh][c] - mx[hh]);
            s += l[hh][c];
        }
        #pragma unroll
        for (int o = 16; o > 0; o >>= 1)
            s += __shfl_xor_sync(0xffffffffu, s, o);
        if (lane == 0) redsm[(hb + hh) * 4 + (w & 3)] = s;
    }
    __syncthreads();
    #pragma unroll
    for (int hh = 0; hh < 4; hh++) {
        const float* p = redsm + (hb + hh) * 4;
        const float rinv = 1.0f / (p[0] + p[1] + p[2] + p[3]);
        float* arow = attn + (((size_t)b * H_ + hb + hh) * S_ + i) * S_;
        #pragma unroll
        for (int c = 0; c < 8; c++)
            arow[c * K2_CHUNK + jl] = l[hh][c] * rinv;
    }
}

// ---------------------------------------------------------------------------
// K3 (K1 CLONE with 16-way j-split): out += attnT-slice @ vt-slice.
// Tile 128i x 64n per CTA over one 64-j slice; single-shot cp8 staging,
// one sync, 32 straight jp iterations (12 LDS.64 : 32 FMA2), 256 threads,
// 2 CTAs/SM, grid (16 j-splits, 8 i-tiles, 16 bh) = 2048. Epilogue: REDG
// (atomicAdd, no return) accumulates the 16 j-partials; out pre-zeroed.
// ---------------------------------------------------------------------------
static constexpr int K3_PITCH = 66;
static constexpr int K3_SMEM = (128 + 64) * K3_PITCH * 4;   // 50688 B

__global__ void __launch_bounds__(256, 2) k3_av(const float* __restrict__ attn,
                                                float* __restrict__ out)
{
    extern __shared__ float sm3[];
    float* As = sm3;                    // [128][66]  attn[i][j-slice]
    float* Vs = sm3 + 128 * K3_PITCH;   // [64][66]   vt[n][j-slice]

    const int jb = blockIdx.x * 64;     // j-split
    const int i0 = blockIdx.y * 128;
    const int bh = blockIdx.z;
    const float* ab = attn + ((size_t)bh * S_ + i0) * S_;
    const float* vtb = g_vt + (size_t)bh * DV_ * S_;
    const int t = threadIdx.x;
    const uint32_t as_u = s2u(As), vs_u = s2u(Vs);

    #pragma unroll
    for (int m = 0; m < 16; m++) {
        const int idx = m * 256 + t;
        const int row = idx >> 5, p = idx & 31;
        cp8(as_u + (uint32_t)(row * K3_PITCH + 2 * p) * 4u,
            ab + (size_t)row * S_ + jb + 2 * p);
    }
    #pragma unroll
    for (int m = 0; m < 8; m++) {
        const int idx = m * 256 + t;
        const int row = idx >> 5, p = idx & 31;
        cp8(vs_u + (uint32_t)(row * K3_PITCH + 2 * p) * 4u,
            vtb + (size_t)row * S_ + jb + 2 * p);
    }
    CP_COMMIT();
    CP_WAIT0();
    __syncthreads();

    const int tx = t & 15;
    const int ty = t >> 4;
    const float* ap = As + (ty * 8) * K3_PITCH;
    const float* vp = Vs + tx * K3_PITCH;

    unsigned long long acc[8][4] = {};

    #pragma unroll 8
    for (int jp = 0; jp < 32; jp++) {
        unsigned long long vv[4], av[8];
        #pragma unroll
        for (int s = 0; s < 4; s++)
            vv[s] = *(const unsigned long long*)(vp + (16 * s) * K3_PITCH + 2 * jp);
        #pragma unroll
        for (int r = 0; r < 8; r++)
            av[r] = *(const unsigned long long*)(ap + r * K3_PITCH + 2 * jp);
        #pragma unroll
        for (int r = 0; r < 8; r++)
            #pragma unroll
            for (int s = 0; s < 4; s++)
                FMA2(acc[r][s], av[r], vv[s]);
    }

    #pragma unroll
    for (int r = 0; r < 8; r++) {
        float* orow = out + ((size_t)bh * S_ + i0 + ty * 8 + r) * DV_;
        #pragma unroll
        for (int s = 0; s < 4; s++) {
            float2 pv = unpack2(acc[r][s]);
            atomicAdd(orow + tx + 16 * s, pv.x + pv.y);   // REDG, no return
        }
    }
}

// ---------------------------------------------------------------------------
extern "C" void kernel_launch(void* const* d_in, const int* in_sizes, int n_in,
                              void* d_out, int out_size)
{
    const float* q    = (const float*)d_in[0];
    const float* k    = (const float*)d_in[1];
    const float* v    = (const float*)d_in[2];
    const int*   mask = (const int*)d_in[3];
    const float* rpr  = (const float*)d_in[4];
    float* out  = (float*)d_out;
    float* attn = out + OUT_ATTN_OFF;

    cudaFuncSetAttribute(k1_qk, cudaFuncAttributeMaxDynamicSharedMemorySize, K1_SMEM);
    cudaFuncSetAttribute(k2_rpr_softmax, cudaFuncAttributeMaxDynamicSharedMemorySize,
                         K2_SMEM);
    cudaFuncSetAttribute(k3_av, cudaFuncAttributeMaxDynamicSharedMemorySize, K3_SMEM);

    {   // launch 0 — K1: attn1 logits into attn region
        dim3 grid(S_ / 64, S_ / 128, B_ * H_);
        k1_qk<<<grid, 256, K1_SMEM>>>(q, k, attn);
    }
    {   // launch 1 — K0t: transpose v into g_vt + zero-init out
        dim3 grid(S_ / 64, B_ * H_);
        k0_vt<<<grid, 256>>>(v, out);
    }
    {   // launch 2 — K2: + positional term, mask, softmax
        dim3 grid(S_, B_);
        k2_rpr_softmax<<<grid, 256, K2_SMEM>>>(q, rpr, mask, attn);
    }
    {   // launch 3 (profiled) — K3: out += attn @ v (16-way j-split, REDG)
        dim3 grid(16, S_ / 128, B_ * H_);
        k3_av<<<grid, 256, K3_SMEM>>>(attn, out);
    }
}